// round 7
// baseline (speedup 1.0000x reference)
#include <cuda_runtime.h>
#include <cuda_fp16.h>
#include <cstdint>

// ---------------------------------------------------------------------------
// CTDExplainer: 3-layer relational GCN explainer. N=8192, D=64, R=3, E=262144.
// Round 7: LayerNorm folded into ngemm_all (row-local, smem-resident),
// agg ping-pong buffers, zgemm MMA reorder for accumulator RAW distance
// (bit-identical numerics). 2-term fp16 split kept (rel_err ~7e-4, monitor).
// Output layout: [ H (N*64) | z0 (N*N) | z1 | z2 ]  fp32.
// ---------------------------------------------------------------------------

#define MAXN 8192
#define MAXE 262144
#define D 64

__device__ float g_H   [MAXN * D];
__device__ float g_HW  [3 * MAXN * D];
__device__ float g_aggA[MAXN * D];
__device__ float g_aggB[MAXN * D];
__device__ uint2 g_hbhi[MAXN * D / 4];   // fp16 splits (4 halfs per uint2)
__device__ uint2 g_hblo[MAXN * D / 4];
__device__ uint2 g_hhi [MAXN * D / 4];

// ---------------- concat x|emb into H (+ fp16 hi for layer-0 B operand) -----
__global__ void concat_split(const float* __restrict__ x, const float* __restrict__ emb,
                             float* __restrict__ H, uint2* __restrict__ hhi,
                             int nx_elems, int total_elems) {
    int i = (blockIdx.x * blockDim.x + threadIdx.x) * 4;
    if (i >= total_elems) return;
    float4 v = (i < nx_elems) ? *(const float4*)(x + i)
                              : *(const float4*)(emb + (i - nx_elems));
    *(float4*)(H + i) = v;
    __half2 h01 = __halves2half2(__float2half_rn(v.x), __float2half_rn(v.y));
    __half2 h23 = __halves2half2(__float2half_rn(v.z), __float2half_rn(v.w));
    uint2 ho;
    ho.x = *(uint32_t*)&h01; ho.y = *(uint32_t*)&h23;
    hhi[i >> 2] = ho;
}

// ---------------- fused per-layer small GEMMs + inline LayerNorm -------------
// grid = (N/32, 5). In = raw pre-LN input (concat-H for layer0, prev agg else).
// Per block: load 32 rows, apply LN (if lng), then blockIdx.y selects:
//   0: Hb = LN(In) @ bilin -> hbhi/hblo; also exports hhi = fp16(LN(In))
//   1..3: HW[y-1] = act(LN(In)) @ W_rel[y-1]
//   4: agg = act(LN(In)) @ W_root + bias
__global__ void __launch_bounds__(256) ngemm_all(
    const float* __restrict__ In, const float* __restrict__ lng,
    const float* __restrict__ lnb, const float* __restrict__ bilin,
    const float* __restrict__ Wrel, const float* __restrict__ Wroot,
    const float* __restrict__ bias, __half* __restrict__ hbhi,
    __half* __restrict__ hblo, __half2* __restrict__ hhi,
    float* __restrict__ HW, float* __restrict__ agg, int relu, int N) {
    __shared__ float Ws[64][64];
    __shared__ float Is[32][65];
    const int tid  = threadIdx.x;
    const int row0 = blockIdx.x * 32;
    const int o    = blockIdx.y;

    const float* W = (o == 0) ? bilin : (o < 4) ? Wrel + (size_t)(o - 1) * 4096 : Wroot;
    const int act = (o > 0) ? relu : 0;

    for (int i = tid; i < 64 * 64; i += 256) Ws[i >> 6][i & 63] = W[i];
    for (int i = tid; i < 32 * 64; i += 256)
        Is[i >> 6][i & 63] = In[(size_t)(row0 + (i >> 6)) * 64 + (i & 63)];
    __syncthreads();

    const int lrow = tid >> 3;       // 0..31, one row per 8 threads
    const int l8   = tid & 7;
    if (lng) {
        float v[8];
        float s = 0.f, q = 0.f;
#pragma unroll
        for (int j = 0; j < 8; j++) {
            v[j] = Is[lrow][l8 * 8 + j];
            s += v[j]; q += v[j] * v[j];
        }
#pragma unroll
        for (int off = 4; off; off >>= 1) {
            s += __shfl_xor_sync(0xffffffffu, s, off);
            q += __shfl_xor_sync(0xffffffffu, q, off);
        }
        float mu  = s * (1.f / 64.f);
        float inv = rsqrtf(q * (1.f / 64.f) - mu * mu + 1e-5f);
#pragma unroll
        for (int j = 0; j < 8; j++) {
            int c = l8 * 8 + j;
            Is[lrow][c] = (v[j] - mu) * inv * lng[c] + lnb[c];
        }
    }
    if (o == 0) {
        if (lng) {   // layer0 hhi comes from concat_split
#pragma unroll
            for (int j = 0; j < 4; j++) {
                int c = l8 * 8 + 2 * j;
                hhi[((size_t)(row0 + lrow) * 64 + c) >> 1] =
                    __halves2half2(__float2half_rn(Is[lrow][c]),
                                   __float2half_rn(Is[lrow][c + 1]));
            }
        }
    } else if (act) {
#pragma unroll
        for (int j = 0; j < 8; j++) {
            int c = l8 * 8 + j;
            Is[lrow][c] = fmaxf(Is[lrow][c], 0.f);
        }
    }
    __syncthreads();

    const int c  = tid & 63;
    const int r0 = tid >> 6;
    float acc[8];
    float bv = (o == 4) ? bias[c] : 0.f;
#pragma unroll
    for (int i = 0; i < 8; i++) acc[i] = bv;
#pragma unroll
    for (int k = 0; k < 64; k++) {
        float w = Ws[k][c];
#pragma unroll
        for (int i = 0; i < 8; i++) acc[i] += Is[r0 + i * 4][k] * w;
    }

    if (o == 0) {
#pragma unroll
        for (int i = 0; i < 8; i++) {
            size_t idx = (size_t)(row0 + r0 + i * 4) * 64 + c;
            __half h = __float2half_rn(acc[i]);
            hbhi[idx] = h;
            hblo[idx] = __float2half_rn(acc[i] - __half2float(h));
        }
    } else if (o < 4) {
        float* Out = HW + (size_t)(o - 1) * N * 64;
#pragma unroll
        for (int i = 0; i < 8; i++)
            Out[(size_t)(row0 + r0 + i * 4) * 64 + c] = acc[i];
    } else {
#pragma unroll
        for (int i = 0; i < 8; i++)
            agg[(size_t)(row0 + r0 + i * 4) * 64 + c] = acc[i];
    }
}

// ---------------- HMMA big GEMM: C = (Ahi + Alo) @ Bhi^T --------------------
// 128x128 CTA tile, 256 thr (8 warps: 4m x 2n), warp tile 32x64, 2 terms.
// MMAs grouped per term (16 Ahi then 16 Alo per kc): same-acc RAW distance 16,
// per-accumulator add order identical to round 6 (bit-exact).
#define TILEB 16384
#define SM_TOT (3 * TILEB)

__device__ __forceinline__ uint32_t smem_u32(const void* p) {
    uint32_t a;
    asm("{ .reg .u64 t; cvta.to.shared.u64 t, %1; cvt.u32.u64 %0, t; }" : "=r"(a) : "l"(p));
    return a;
}
__device__ __forceinline__ void ldm_x4(uint32_t& r0, uint32_t& r1, uint32_t& r2,
                                       uint32_t& r3, uint32_t addr) {
    asm volatile("ldmatrix.sync.aligned.m8n8.x4.shared.b16 {%0,%1,%2,%3}, [%4];"
                 : "=r"(r0), "=r"(r1), "=r"(r2), "=r"(r3) : "r"(addr));
}
__device__ __forceinline__ void mma16816(float* c, const uint32_t* a,
                                         uint32_t b0, uint32_t b1) {
    asm volatile(
        "mma.sync.aligned.m16n8k16.row.col.f32.f16.f16.f32 "
        "{%0,%1,%2,%3}, {%4,%5,%6,%7}, {%8,%9}, {%0,%1,%2,%3};"
        : "+f"(c[0]), "+f"(c[1]), "+f"(c[2]), "+f"(c[3])
        : "r"(a[0]), "r"(a[1]), "r"(a[2]), "r"(a[3]), "r"(b0), "r"(b1));
}

__global__ void __launch_bounds__(256, 2) zgemm_mma(
    const __half* __restrict__ Ahi, const __half* __restrict__ Alo,
    const __half* __restrict__ Bhi, float* __restrict__ C, int N) {
    extern __shared__ __align__(16) char smem[];
    const int tid = threadIdx.x;
    const int m0 = blockIdx.y * 128, n0 = blockIdx.x * 128;

    {
        const int row = tid >> 1;
        const int cu  = (tid & 1) * 4;
        const int r7  = row & 7;
        const __half* gA0 = Ahi + (size_t)(m0 + row) * 64 + (tid & 1) * 32;
        const __half* gA1 = Alo + (size_t)(m0 + row) * 64 + (tid & 1) * 32;
        const __half* gB0 = Bhi + (size_t)(n0 + row) * 64 + (tid & 1) * 32;
        char* s = smem + row * 128;
#pragma unroll
        for (int i = 0; i < 4; i++) {
            int off = ((cu + i) ^ r7) << 4;
            *(uint4*)(s + 0 * TILEB + off) = *(const uint4*)(gA0 + i * 8);
            *(uint4*)(s + 1 * TILEB + off) = *(const uint4*)(gA1 + i * 8);
            *(uint4*)(s + 2 * TILEB + off) = *(const uint4*)(gB0 + i * 8);
        }
    }
    __syncthreads();

    const int lane = tid & 31;
    const int wid  = tid >> 5;
    const int wm   = (wid & 3) * 32;
    const int wn   = (wid >> 2) * 64;
    const uint32_t sb = smem_u32(smem);

    const int a_row = wm + (lane & 15);
    const int a_r7  = a_row & 7;
    const int au    = lane >> 4;
    const uint32_t abase_row = sb + a_row * 128;
    const int b_row = wn + (lane & 7) + (((lane >> 4) & 1) << 3);
    const int b_r7  = b_row & 7;
    const int bu    = (lane >> 3) & 1;
    const uint32_t bbase_row = sb + 2 * TILEB + b_row * 128;

    float acc[16][4];
#pragma unroll
    for (int i = 0; i < 16; i++)
#pragma unroll
        for (int j = 0; j < 4; j++) acc[i][j] = 0.f;

#pragma unroll
    for (int kc = 0; kc < 4; kc++) {
        const uint32_t aoffk = ((((kc << 1) + au) ^ a_r7) << 4);
        const uint32_t boffk = ((((kc << 1) + bu) ^ b_r7) << 4);
        uint32_t Ah[8], Al[8], bh[16];
        ldm_x4(Ah[0], Ah[1], Ah[2], Ah[3], abase_row + aoffk);
        ldm_x4(Ah[4], Ah[5], Ah[6], Ah[7], abase_row + aoffk + 16 * 128);
        ldm_x4(Al[0], Al[1], Al[2], Al[3], abase_row + TILEB + aoffk);
        ldm_x4(Al[4], Al[5], Al[6], Al[7], abase_row + TILEB + aoffk + 16 * 128);
#pragma unroll
        for (int nt = 0; nt < 4; nt++)
            ldm_x4(bh[4 * nt], bh[4 * nt + 1], bh[4 * nt + 2], bh[4 * nt + 3],
                   bbase_row + boffk + nt * 16 * 128);
        // term Ahi*Bhi (16 MMAs, all accs distinct)
#pragma unroll
        for (int nt = 0; nt < 4; nt++) {
            mma16816(acc[2 * nt],         Ah,     bh[4 * nt],     bh[4 * nt + 1]);
            mma16816(acc[2 * nt + 1],     Ah,     bh[4 * nt + 2], bh[4 * nt + 3]);
            mma16816(acc[8 + 2 * nt],     Ah + 4, bh[4 * nt],     bh[4 * nt + 1]);
            mma16816(acc[8 + 2 * nt + 1], Ah + 4, bh[4 * nt + 2], bh[4 * nt + 3]);
        }
        // term Alo*Bhi
#pragma unroll
        for (int nt = 0; nt < 4; nt++) {
            mma16816(acc[2 * nt],         Al,     bh[4 * nt],     bh[4 * nt + 1]);
            mma16816(acc[2 * nt + 1],     Al,     bh[4 * nt + 2], bh[4 * nt + 3]);
            mma16816(acc[8 + 2 * nt],     Al + 4, bh[4 * nt],     bh[4 * nt + 1]);
            mma16816(acc[8 + 2 * nt + 1], Al + 4, bh[4 * nt + 2], bh[4 * nt + 3]);
        }
    }

    const int er = lane >> 2;
    const int ec = (lane & 3) * 2;
#pragma unroll
    for (int mi = 0; mi < 2; mi++)
#pragma unroll
        for (int ni = 0; ni < 8; ni++) {
            float* f = acc[mi * 8 + ni];
            size_t r = (size_t)(m0 + wm + mi * 16 + er);
            int col = n0 + wn + ni * 8 + ec;
            *(float2*)(C + r * N + col)       = make_float2(f[0], f[1]);
            *(float2*)(C + (r + 8) * N + col) = make_float2(f[2], f[3]);
        }
}

// ---------------- fused edge gather + scatter (16 lanes/edge, v4 red) -------
__global__ void edge_fused(const float* __restrict__ Z, const float* __restrict__ HW,
                           const int* __restrict__ row, const int* __restrict__ col,
                           const int* __restrict__ et, const float* __restrict__ ev,
                           float* __restrict__ agg, int E, int N) {
    int gi  = blockIdx.x * blockDim.x + threadIdx.x;
    int e   = gi >> 4;
    int sub = threadIdx.x & 15;
    if (e >= E) return;
    int r = row[e], c = col[e], t = et[e];
    float av = Z[(size_t)r * N + c] * ev[e];
    float4 m = ((const float4*)(HW + ((size_t)t * N + c) * 64))[sub];
    float* dst = agg + (size_t)r * 64 + sub * 4;
    asm volatile("red.global.add.v4.f32 [%0], {%1, %2, %3, %4};"
                 :: "l"(dst), "f"(m.x * av), "f"(m.y * av),
                    "f"(m.z * av), "f"(m.w * av) : "memory");
}

// ---------------------------------------------------------------------------
extern "C" void kernel_launch(void* const* d_in, const int* in_sizes, int n_in,
                              void* d_out, int out_size) {
    const float* x       = (const float*)d_in[0];
    const float* emb     = (const float*)d_in[1];
    const float* bilin   = (const float*)d_in[2];
    const float* eval    = (const float*)d_in[3];
    const float* W_root  = (const float*)d_in[4];
    const float* W_rel   = (const float*)d_in[5];
    const float* bias    = (const float*)d_in[6];
    const float* ln_g    = (const float*)d_in[7];
    const float* ln_b    = (const float*)d_in[8];
    const int*   erow    = (const int*)d_in[9];
    const int*   ecol    = (const int*)d_in[10];
    const int*   etype   = (const int*)d_in[11];

    const int NX = in_sizes[0] / D;
    const int NE = in_sizes[1] / D;
    const int N  = NX + NE;
    const int E  = in_sizes[3];

    float* out   = (float*)d_out;
    float* Hout  = out;
    float* Zbase = out + (size_t)N * D;

    float *H, *HW, *aggA, *aggB;
    uint2 *hbhi, *hblo, *hhi;
    cudaGetSymbolAddress((void**)&H,    g_H);
    cudaGetSymbolAddress((void**)&HW,   g_HW);
    cudaGetSymbolAddress((void**)&aggA, g_aggA);
    cudaGetSymbolAddress((void**)&aggB, g_aggB);
    cudaGetSymbolAddress((void**)&hbhi, g_hbhi);
    cudaGetSymbolAddress((void**)&hblo, g_hblo);
    cudaGetSymbolAddress((void**)&hhi,  g_hhi);

    cudaFuncSetAttribute(zgemm_mma, cudaFuncAttributeMaxDynamicSharedMemorySize, SM_TOT);

    // H = concat(x, emb) + fp16 hi (layer-0 zgemm B operand)
    {
        int total = N * D;
        int blocks = (total / 4 + 255) / 256;
        concat_split<<<blocks, 256>>>(x, emb, H, hhi, NX * D, total);
    }

    dim3 zgrid(N / 128, N / 128);
    dim3 ngrid(N / 32, 5);
    const int edge_blocks = (E * 16 + 255) / 256;

    // per-layer plumbing: In (pre-LN), LN params (null = no LN), agg target
    const float* ins[3]  = { H, aggA, aggB };
    float*       outs[3] = { aggA, aggB, Hout };

    for (int l = 0; l < 3; l++) {
        float* Zl   = Zbase + (size_t)l * N * N;
        const float* lng = (l == 0) ? nullptr : ln_g + (size_t)(l - 1) * D;
        const float* lnb = (l == 0) ? nullptr : ln_b + (size_t)(l - 1) * D;
        int relu = (l > 0) ? 1 : 0;

        // LN + Hb(hi/lo) + hhi + HW[0..2] + agg (parallel over outputs)
        ngemm_all<<<ngrid, 256>>>(ins[l], lng, lnb,
                                  bilin + (size_t)l * D * D,
                                  W_rel + (size_t)l * 3 * D * D,
                                  W_root + (size_t)l * D * D,
                                  bias + (size_t)l * D,
                                  (__half*)hbhi, (__half*)hblo, (__half2*)hhi,
                                  HW, outs[l], relu, N);
        // Z = (Hbhi + Hblo) @ Hhi^T via HMMA 2-term
        zgemm_mma<<<zgrid, 256, SM_TOT>>>((const __half*)hbhi, (const __half*)hblo,
                                          (const __half*)hhi, Zl, N);
        // agg[row] += HW[etype, col] * (Z[row,col] * ev)
        edge_fused<<<edge_blocks, 256>>>(Zl, HW, erow, ecol, etype, eval, outs[l], E, N);
    }
}

// round 8
// speedup vs baseline: 1.0435x; 1.0435x over previous
#include <cuda_runtime.h>
#include <cuda_fp16.h>
#include <cstdint>

// ---------------------------------------------------------------------------
// CTDExplainer: 3-layer relational GCN explainer. N=8192, D=64, R=3, E=262144.
// Round 8: persistent zgemm with cp.async double-buffered operand prefetch
// (hides L2 load latency + wave transitions). MMA math bit-identical to r6/r7.
// Output layout: [ H (N*64) | z0 (N*N) | z1 | z2 ]  fp32.
// ---------------------------------------------------------------------------

#define MAXN 8192
#define MAXE 262144
#define D 64

__device__ float g_H   [MAXN * D];
__device__ float g_HW  [3 * MAXN * D];
__device__ float g_aggA[MAXN * D];
__device__ float g_aggB[MAXN * D];
__device__ uint2 g_hbhi[MAXN * D / 4];
__device__ uint2 g_hblo[MAXN * D / 4];
__device__ uint2 g_hhi [MAXN * D / 4];

// ---------------- concat x|emb into H (+ fp16 hi for layer-0 B operand) -----
__global__ void concat_split(const float* __restrict__ x, const float* __restrict__ emb,
                             float* __restrict__ H, uint2* __restrict__ hhi,
                             int nx_elems, int total_elems) {
    int i = (blockIdx.x * blockDim.x + threadIdx.x) * 4;
    if (i >= total_elems) return;
    float4 v = (i < nx_elems) ? *(const float4*)(x + i)
                              : *(const float4*)(emb + (i - nx_elems));
    *(float4*)(H + i) = v;
    __half2 h01 = __halves2half2(__float2half_rn(v.x), __float2half_rn(v.y));
    __half2 h23 = __halves2half2(__float2half_rn(v.z), __float2half_rn(v.w));
    uint2 ho;
    ho.x = *(uint32_t*)&h01; ho.y = *(uint32_t*)&h23;
    hhi[i >> 2] = ho;
}

// ---------------- fused per-layer small GEMMs + inline LayerNorm -------------
__global__ void __launch_bounds__(256) ngemm_all(
    const float* __restrict__ In, const float* __restrict__ lng,
    const float* __restrict__ lnb, const float* __restrict__ bilin,
    const float* __restrict__ Wrel, const float* __restrict__ Wroot,
    const float* __restrict__ bias, __half* __restrict__ hbhi,
    __half* __restrict__ hblo, __half2* __restrict__ hhi,
    float* __restrict__ HW, float* __restrict__ agg, int relu, int N) {
    __shared__ float Ws[64][64];
    __shared__ float Is[32][65];
    const int tid  = threadIdx.x;
    const int row0 = blockIdx.x * 32;
    const int o    = blockIdx.y;

    const float* W = (o == 0) ? bilin : (o < 4) ? Wrel + (size_t)(o - 1) * 4096 : Wroot;
    const int act = (o > 0) ? relu : 0;

    for (int i = tid; i < 64 * 64; i += 256) Ws[i >> 6][i & 63] = W[i];
    for (int i = tid; i < 32 * 64; i += 256)
        Is[i >> 6][i & 63] = In[(size_t)(row0 + (i >> 6)) * 64 + (i & 63)];
    __syncthreads();

    const int lrow = tid >> 3;
    const int l8   = tid & 7;
    if (lng) {
        float v[8];
        float s = 0.f, q = 0.f;
#pragma unroll
        for (int j = 0; j < 8; j++) {
            v[j] = Is[lrow][l8 * 8 + j];
            s += v[j]; q += v[j] * v[j];
        }
#pragma unroll
        for (int off = 4; off; off >>= 1) {
            s += __shfl_xor_sync(0xffffffffu, s, off);
            q += __shfl_xor_sync(0xffffffffu, q, off);
        }
        float mu  = s * (1.f / 64.f);
        float inv = rsqrtf(q * (1.f / 64.f) - mu * mu + 1e-5f);
#pragma unroll
        for (int j = 0; j < 8; j++) {
            int c = l8 * 8 + j;
            Is[lrow][c] = (v[j] - mu) * inv * lng[c] + lnb[c];
        }
    }
    if (o == 0) {
        if (lng) {
#pragma unroll
            for (int j = 0; j < 4; j++) {
                int c = l8 * 8 + 2 * j;
                hhi[((size_t)(row0 + lrow) * 64 + c) >> 1] =
                    __halves2half2(__float2half_rn(Is[lrow][c]),
                                   __float2half_rn(Is[lrow][c + 1]));
            }
        }
    } else if (act) {
#pragma unroll
        for (int j = 0; j < 8; j++) {
            int c = l8 * 8 + j;
            Is[lrow][c] = fmaxf(Is[lrow][c], 0.f);
        }
    }
    __syncthreads();

    const int c  = tid & 63;
    const int r0 = tid >> 6;
    float acc[8];
    float bv = (o == 4) ? bias[c] : 0.f;
#pragma unroll
    for (int i = 0; i < 8; i++) acc[i] = bv;
#pragma unroll
    for (int k = 0; k < 64; k++) {
        float w = Ws[k][c];
#pragma unroll
        for (int i = 0; i < 8; i++) acc[i] += Is[r0 + i * 4][k] * w;
    }

    if (o == 0) {
#pragma unroll
        for (int i = 0; i < 8; i++) {
            size_t idx = (size_t)(row0 + r0 + i * 4) * 64 + c;
            __half h = __float2half_rn(acc[i]);
            hbhi[idx] = h;
            hblo[idx] = __float2half_rn(acc[i] - __half2float(h));
        }
    } else if (o < 4) {
        float* Out = HW + (size_t)(o - 1) * N * 64;
#pragma unroll
        for (int i = 0; i < 8; i++)
            Out[(size_t)(row0 + r0 + i * 4) * 64 + c] = acc[i];
    } else {
#pragma unroll
        for (int i = 0; i < 8; i++)
            agg[(size_t)(row0 + r0 + i * 4) * 64 + c] = acc[i];
    }
}

// ---------------- persistent HMMA GEMM: C = (Ahi + Alo) @ Bhi^T -------------
// Grid = 2 CTAs/SM persistent; each CTA loops over tiles with double-buffered
// cp.async operand prefetch. 128x128 tile, 8 warps, warp tile 32x64, 2 terms.
#define TILEB 16384
#define STAGEB (3 * TILEB)          // 48KB per stage
#define SM_TOT (2 * STAGEB)         // 96KB

__device__ __forceinline__ uint32_t smem_u32(const void* p) {
    uint32_t a;
    asm("{ .reg .u64 t; cvta.to.shared.u64 t, %1; cvt.u32.u64 %0, t; }" : "=r"(a) : "l"(p));
    return a;
}
__device__ __forceinline__ void ldm_x4(uint32_t& r0, uint32_t& r1, uint32_t& r2,
                                       uint32_t& r3, uint32_t addr) {
    asm volatile("ldmatrix.sync.aligned.m8n8.x4.shared.b16 {%0,%1,%2,%3}, [%4];"
                 : "=r"(r0), "=r"(r1), "=r"(r2), "=r"(r3) : "r"(addr));
}
__device__ __forceinline__ void mma16816(float* c, const uint32_t* a,
                                         uint32_t b0, uint32_t b1) {
    asm volatile(
        "mma.sync.aligned.m16n8k16.row.col.f32.f16.f16.f32 "
        "{%0,%1,%2,%3}, {%4,%5,%6,%7}, {%8,%9}, {%0,%1,%2,%3};"
        : "+f"(c[0]), "+f"(c[1]), "+f"(c[2]), "+f"(c[3])
        : "r"(a[0]), "r"(a[1]), "r"(a[2]), "r"(a[3]), "r"(b0), "r"(b1));
}
__device__ __forceinline__ void cpa16(uint32_t saddr, const void* gaddr) {
    asm volatile("cp.async.cg.shared.global [%0], [%1], 16;"
                 :: "r"(saddr), "l"(gaddr));
}

__global__ void __launch_bounds__(256, 2) zgemm_mma(
    const __half* __restrict__ Ahi, const __half* __restrict__ Alo,
    const __half* __restrict__ Bhi, float* __restrict__ C, int N,
    int tiles_n, int total_tiles) {
    extern __shared__ __align__(16) char smem[];
    const int tid = threadIdx.x;
    const uint32_t sb = smem_u32(smem);

    // per-thread load slots (fixed across tiles)
    const int lrow = tid >> 1;
    const int lcu  = (tid & 1) * 4;
    const int lr7  = lrow & 7;
    const int lcol = (tid & 1) * 32;       // half-column offset in source row
    uint32_t soff[4];
#pragma unroll
    for (int i = 0; i < 4; i++)
        soff[i] = lrow * 128 + (((lcu + i) ^ lr7) << 4);

    // issue loads of tile t into stage buf
    auto issue = [&](int buf, int t) {
        const int m0 = (t >> 6) * 128;       // tiles_n == 64 assumed via shift
        const int n0 = (t & 63) * 128;
        const uint32_t s0 = sb + buf * STAGEB;
        const __half* gA0 = Ahi + (size_t)(m0 + lrow) * 64 + lcol;
        const __half* gA1 = Alo + (size_t)(m0 + lrow) * 64 + lcol;
        const __half* gB0 = Bhi + (size_t)(n0 + lrow) * 64 + lcol;
#pragma unroll
        for (int i = 0; i < 4; i++) {
            cpa16(s0 + 0 * TILEB + soff[i], gA0 + i * 8);
            cpa16(s0 + 1 * TILEB + soff[i], gA1 + i * 8);
            cpa16(s0 + 2 * TILEB + soff[i], gB0 + i * 8);
        }
    };

    const int lane = tid & 31;
    const int wid  = tid >> 5;
    const int wm   = (wid & 3) * 32;
    const int wn   = (wid >> 2) * 64;

    const int a_row = wm + (lane & 15);
    const int a_r7  = a_row & 7;
    const int au    = lane >> 4;
    const int b_row = wn + (lane & 7) + (((lane >> 4) & 1) << 3);
    const int b_r7  = b_row & 7;
    const int bu    = (lane >> 3) & 1;
    const int er = lane >> 2;
    const int ec = (lane & 3) * 2;

    int t0 = blockIdx.x;
    const int stride = gridDim.x;
    if (t0 >= total_tiles) return;

    issue(0, t0);
    asm volatile("cp.async.commit_group;");

    int idx = 0;
    for (int t = t0; t < total_tiles; t += stride, idx++) {
        const int buf = idx & 1;
        const int nt = t + stride;
        if (nt < total_tiles) issue(1 - buf, nt);
        asm volatile("cp.async.commit_group;");
        asm volatile("cp.async.wait_group 1;");
        __syncthreads();

        const uint32_t s0 = sb + buf * STAGEB;
        const uint32_t abase_row = s0 + a_row * 128;
        const uint32_t bbase_row = s0 + 2 * TILEB + b_row * 128;

        float acc[16][4];
#pragma unroll
        for (int i = 0; i < 16; i++)
#pragma unroll
            for (int j = 0; j < 4; j++) acc[i][j] = 0.f;

#pragma unroll
        for (int kc = 0; kc < 4; kc++) {
            const uint32_t aoffk = ((((kc << 1) + au) ^ a_r7) << 4);
            const uint32_t boffk = ((((kc << 1) + bu) ^ b_r7) << 4);
            uint32_t Ah[8], Al[8], bh[16];
            ldm_x4(Ah[0], Ah[1], Ah[2], Ah[3], abase_row + aoffk);
            ldm_x4(Ah[4], Ah[5], Ah[6], Ah[7], abase_row + aoffk + 16 * 128);
            ldm_x4(Al[0], Al[1], Al[2], Al[3], abase_row + TILEB + aoffk);
            ldm_x4(Al[4], Al[5], Al[6], Al[7], abase_row + TILEB + aoffk + 16 * 128);
#pragma unroll
            for (int nt2 = 0; nt2 < 4; nt2++)
                ldm_x4(bh[4 * nt2], bh[4 * nt2 + 1], bh[4 * nt2 + 2], bh[4 * nt2 + 3],
                       bbase_row + boffk + nt2 * 16 * 128);
#pragma unroll
            for (int nt2 = 0; nt2 < 4; nt2++) {
                mma16816(acc[2 * nt2],         Ah,     bh[4 * nt2],     bh[4 * nt2 + 1]);
                mma16816(acc[2 * nt2 + 1],     Ah,     bh[4 * nt2 + 2], bh[4 * nt2 + 3]);
                mma16816(acc[8 + 2 * nt2],     Ah + 4, bh[4 * nt2],     bh[4 * nt2 + 1]);
                mma16816(acc[8 + 2 * nt2 + 1], Ah + 4, bh[4 * nt2 + 2], bh[4 * nt2 + 3]);
            }
#pragma unroll
            for (int nt2 = 0; nt2 < 4; nt2++) {
                mma16816(acc[2 * nt2],         Al,     bh[4 * nt2],     bh[4 * nt2 + 1]);
                mma16816(acc[2 * nt2 + 1],     Al,     bh[4 * nt2 + 2], bh[4 * nt2 + 3]);
                mma16816(acc[8 + 2 * nt2],     Al + 4, bh[4 * nt2],     bh[4 * nt2 + 1]);
                mma16816(acc[8 + 2 * nt2 + 1], Al + 4, bh[4 * nt2 + 2], bh[4 * nt2 + 3]);
            }
        }

        const int m0 = (t >> 6) * 128;
        const int n0 = (t & 63) * 128;
#pragma unroll
        for (int mi = 0; mi < 2; mi++)
#pragma unroll
            for (int ni = 0; ni < 8; ni++) {
                float* f = acc[mi * 8 + ni];
                size_t r = (size_t)(m0 + wm + mi * 16 + er);
                int col = n0 + wn + ni * 8 + ec;
                *(float2*)(C + r * N + col)       = make_float2(f[0], f[1]);
                *(float2*)(C + (r + 8) * N + col) = make_float2(f[2], f[3]);
            }
        __syncthreads();   // all reads of buf done before next iter overwrites it
    }
}

// ---------------- fused edge gather + scatter (16 lanes/edge, v4 red) -------
__global__ void edge_fused(const float* __restrict__ Z, const float* __restrict__ HW,
                           const int* __restrict__ row, const int* __restrict__ col,
                           const int* __restrict__ et, const float* __restrict__ ev,
                           float* __restrict__ agg, int E, int N) {
    int gi  = blockIdx.x * blockDim.x + threadIdx.x;
    int e   = gi >> 4;
    int sub = threadIdx.x & 15;
    if (e >= E) return;
    int r = row[e], c = col[e], t = et[e];
    float av = Z[(size_t)r * N + c] * ev[e];
    float4 m = ((const float4*)(HW + ((size_t)t * N + c) * 64))[sub];
    float* dst = agg + (size_t)r * 64 + sub * 4;
    asm volatile("red.global.add.v4.f32 [%0], {%1, %2, %3, %4};"
                 :: "l"(dst), "f"(m.x * av), "f"(m.y * av),
                    "f"(m.z * av), "f"(m.w * av) : "memory");
}

// ---------------------------------------------------------------------------
extern "C" void kernel_launch(void* const* d_in, const int* in_sizes, int n_in,
                              void* d_out, int out_size) {
    const float* x       = (const float*)d_in[0];
    const float* emb     = (const float*)d_in[1];
    const float* bilin   = (const float*)d_in[2];
    const float* eval    = (const float*)d_in[3];
    const float* W_root  = (const float*)d_in[4];
    const float* W_rel   = (const float*)d_in[5];
    const float* bias    = (const float*)d_in[6];
    const float* ln_g    = (const float*)d_in[7];
    const float* ln_b    = (const float*)d_in[8];
    const int*   erow    = (const int*)d_in[9];
    const int*   ecol    = (const int*)d_in[10];
    const int*   etype   = (const int*)d_in[11];

    const int NX = in_sizes[0] / D;
    const int NE = in_sizes[1] / D;
    const int N  = NX + NE;
    const int E  = in_sizes[3];

    float* out   = (float*)d_out;
    float* Hout  = out;
    float* Zbase = out + (size_t)N * D;

    float *H, *HW, *aggA, *aggB;
    uint2 *hbhi, *hblo, *hhi;
    cudaGetSymbolAddress((void**)&H,    g_H);
    cudaGetSymbolAddress((void**)&HW,   g_HW);
    cudaGetSymbolAddress((void**)&aggA, g_aggA);
    cudaGetSymbolAddress((void**)&aggB, g_aggB);
    cudaGetSymbolAddress((void**)&hbhi, g_hbhi);
    cudaGetSymbolAddress((void**)&hblo, g_hblo);
    cudaGetSymbolAddress((void**)&hhi,  g_hhi);

    cudaFuncSetAttribute(zgemm_mma, cudaFuncAttributeMaxDynamicSharedMemorySize, SM_TOT);

    int nsm = 148;
    cudaDeviceGetAttribute(&nsm, cudaDevAttrMultiProcessorCount, 0);

    {
        int total = N * D;
        int blocks = (total / 4 + 255) / 256;
        concat_split<<<blocks, 256>>>(x, emb, H, hhi, NX * D, total);
    }

    const int tiles_n = N / 128;                 // 64
    const int total_tiles = tiles_n * tiles_n;   // 4096
    const int zgrid = 2 * nsm;
    dim3 ngrid(N / 32, 5);
    const int edge_blocks = (E * 16 + 255) / 256;

    const float* ins[3]  = { H, aggA, aggB };
    float*       outs[3] = { aggA, aggB, Hout };

    for (int l = 0; l < 3; l++) {
        float* Zl   = Zbase + (size_t)l * N * N;
        const float* lng = (l == 0) ? nullptr : ln_g + (size_t)(l - 1) * D;
        const float* lnb = (l == 0) ? nullptr : ln_b + (size_t)(l - 1) * D;
        int relu = (l > 0) ? 1 : 0;

        ngemm_all<<<ngrid, 256>>>(ins[l], lng, lnb,
                                  bilin + (size_t)l * D * D,
                                  W_rel + (size_t)l * 3 * D * D,
                                  W_root + (size_t)l * D * D,
                                  bias + (size_t)l * D,
                                  (__half*)hbhi, (__half*)hblo, (__half2*)hhi,
                                  HW, outs[l], relu, N);
        zgemm_mma<<<zgrid, 256, SM_TOT>>>((const __half*)hbhi, (const __half*)hblo,
                                          (const __half*)hhi, Zl, N,
                                          tiles_n, total_tiles);
        edge_fused<<<edge_blocks, 256>>>(Zl, HW, erow, ecol, etype, eval, outs[l], E, N);
    }
}

// round 9
// speedup vs baseline: 1.0957x; 1.0500x over previous
#include <cuda_runtime.h>
#include <cuda_fp16.h>
#include <cstdint>

// ---------------------------------------------------------------------------
// CTDExplainer: 3-layer relational GCN explainer. N=8192, D=64, R=3, E=262144.
// Round 9: edge_fused processes 2 independent edges per 16-lane group (2x MLP
// on the latency-bound Z gather); zgemm hot loop ALU-thinned (hoisted swizzle
// offsets + per-stage bases). zgemm math bit-identical to rounds 6-8.
// Output layout: [ H (N*64) | z0 (N*N) | z1 | z2 ]  fp32.
// ---------------------------------------------------------------------------

#define MAXN 8192
#define MAXE 262144
#define D 64

__device__ float g_H   [MAXN * D];
__device__ float g_HW  [3 * MAXN * D];
__device__ float g_aggA[MAXN * D];
__device__ float g_aggB[MAXN * D];
__device__ uint2 g_hbhi[MAXN * D / 4];
__device__ uint2 g_hblo[MAXN * D / 4];
__device__ uint2 g_hhi [MAXN * D / 4];

// ---------------- concat x|emb into H (+ fp16 hi for layer-0 B operand) -----
__global__ void concat_split(const float* __restrict__ x, const float* __restrict__ emb,
                             float* __restrict__ H, uint2* __restrict__ hhi,
                             int nx_elems, int total_elems) {
    int i = (blockIdx.x * blockDim.x + threadIdx.x) * 4;
    if (i >= total_elems) return;
    float4 v = (i < nx_elems) ? *(const float4*)(x + i)
                              : *(const float4*)(emb + (i - nx_elems));
    *(float4*)(H + i) = v;
    __half2 h01 = __halves2half2(__float2half_rn(v.x), __float2half_rn(v.y));
    __half2 h23 = __halves2half2(__float2half_rn(v.z), __float2half_rn(v.w));
    uint2 ho;
    ho.x = *(uint32_t*)&h01; ho.y = *(uint32_t*)&h23;
    hhi[i >> 2] = ho;
}

// ---------------- fused per-layer small GEMMs + inline LayerNorm -------------
__global__ void __launch_bounds__(256) ngemm_all(
    const float* __restrict__ In, const float* __restrict__ lng,
    const float* __restrict__ lnb, const float* __restrict__ bilin,
    const float* __restrict__ Wrel, const float* __restrict__ Wroot,
    const float* __restrict__ bias, __half* __restrict__ hbhi,
    __half* __restrict__ hblo, __half2* __restrict__ hhi,
    float* __restrict__ HW, float* __restrict__ agg, int relu, int N) {
    __shared__ float Ws[64][64];
    __shared__ float Is[32][65];
    const int tid  = threadIdx.x;
    const int row0 = blockIdx.x * 32;
    const int o    = blockIdx.y;

    const float* W = (o == 0) ? bilin : (o < 4) ? Wrel + (size_t)(o - 1) * 4096 : Wroot;
    const int act = (o > 0) ? relu : 0;

    for (int i = tid; i < 64 * 64; i += 256) Ws[i >> 6][i & 63] = W[i];
    for (int i = tid; i < 32 * 64; i += 256)
        Is[i >> 6][i & 63] = In[(size_t)(row0 + (i >> 6)) * 64 + (i & 63)];
    __syncthreads();

    const int lrow = tid >> 3;
    const int l8   = tid & 7;
    if (lng) {
        float v[8];
        float s = 0.f, q = 0.f;
#pragma unroll
        for (int j = 0; j < 8; j++) {
            v[j] = Is[lrow][l8 * 8 + j];
            s += v[j]; q += v[j] * v[j];
        }
#pragma unroll
        for (int off = 4; off; off >>= 1) {
            s += __shfl_xor_sync(0xffffffffu, s, off);
            q += __shfl_xor_sync(0xffffffffu, q, off);
        }
        float mu  = s * (1.f / 64.f);
        float inv = rsqrtf(q * (1.f / 64.f) - mu * mu + 1e-5f);
#pragma unroll
        for (int j = 0; j < 8; j++) {
            int c = l8 * 8 + j;
            Is[lrow][c] = (v[j] - mu) * inv * lng[c] + lnb[c];
        }
    }
    if (o == 0) {
        if (lng) {
#pragma unroll
            for (int j = 0; j < 4; j++) {
                int c = l8 * 8 + 2 * j;
                hhi[((size_t)(row0 + lrow) * 64 + c) >> 1] =
                    __halves2half2(__float2half_rn(Is[lrow][c]),
                                   __float2half_rn(Is[lrow][c + 1]));
            }
        }
    } else if (act) {
#pragma unroll
        for (int j = 0; j < 8; j++) {
            int c = l8 * 8 + j;
            Is[lrow][c] = fmaxf(Is[lrow][c], 0.f);
        }
    }
    __syncthreads();

    const int c  = tid & 63;
    const int r0 = tid >> 6;
    float acc[8];
    float bv = (o == 4) ? bias[c] : 0.f;
#pragma unroll
    for (int i = 0; i < 8; i++) acc[i] = bv;
#pragma unroll
    for (int k = 0; k < 64; k++) {
        float w = Ws[k][c];
#pragma unroll
        for (int i = 0; i < 8; i++) acc[i] += Is[r0 + i * 4][k] * w;
    }

    if (o == 0) {
#pragma unroll
        for (int i = 0; i < 8; i++) {
            size_t idx = (size_t)(row0 + r0 + i * 4) * 64 + c;
            __half h = __float2half_rn(acc[i]);
            hbhi[idx] = h;
            hblo[idx] = __float2half_rn(acc[i] - __half2float(h));
        }
    } else if (o < 4) {
        float* Out = HW + (size_t)(o - 1) * N * 64;
#pragma unroll
        for (int i = 0; i < 8; i++)
            Out[(size_t)(row0 + r0 + i * 4) * 64 + c] = acc[i];
    } else {
#pragma unroll
        for (int i = 0; i < 8; i++)
            agg[(size_t)(row0 + r0 + i * 4) * 64 + c] = acc[i];
    }
}

// ---------------- persistent HMMA GEMM: C = (Ahi + Alo) @ Bhi^T -------------
#define TILEB 16384
#define STAGEB (3 * TILEB)
#define SM_TOT (2 * STAGEB)

__device__ __forceinline__ uint32_t smem_u32(const void* p) {
    uint32_t a;
    asm("{ .reg .u64 t; cvta.to.shared.u64 t, %1; cvt.u32.u64 %0, t; }" : "=r"(a) : "l"(p));
    return a;
}
__device__ __forceinline__ void ldm_x4(uint32_t& r0, uint32_t& r1, uint32_t& r2,
                                       uint32_t& r3, uint32_t addr) {
    asm volatile("ldmatrix.sync.aligned.m8n8.x4.shared.b16 {%0,%1,%2,%3}, [%4];"
                 : "=r"(r0), "=r"(r1), "=r"(r2), "=r"(r3) : "r"(addr));
}
__device__ __forceinline__ void mma16816(float* c, const uint32_t* a,
                                         uint32_t b0, uint32_t b1) {
    asm volatile(
        "mma.sync.aligned.m16n8k16.row.col.f32.f16.f16.f32 "
        "{%0,%1,%2,%3}, {%4,%5,%6,%7}, {%8,%9}, {%0,%1,%2,%3};"
        : "+f"(c[0]), "+f"(c[1]), "+f"(c[2]), "+f"(c[3])
        : "r"(a[0]), "r"(a[1]), "r"(a[2]), "r"(a[3]), "r"(b0), "r"(b1));
}
__device__ __forceinline__ void cpa16(uint32_t saddr, const void* gaddr) {
    asm volatile("cp.async.cg.shared.global [%0], [%1], 16;"
                 :: "r"(saddr), "l"(gaddr));
}

__global__ void __launch_bounds__(256, 2) zgemm_mma(
    const __half* __restrict__ Ahi, const __half* __restrict__ Alo,
    const __half* __restrict__ Bhi, float* __restrict__ C, int N,
    int total_tiles) {
    extern __shared__ __align__(16) char smem[];
    const int tid = threadIdx.x;
    const uint32_t sb = smem_u32(smem);

    // per-thread cp.async slots (tile-invariant)
    const int lrow = tid >> 1;
    const int lcu  = (tid & 1) * 4;
    const int lr7  = lrow & 7;
    const int lcol = (tid & 1) * 32;
    uint32_t soff[4];
#pragma unroll
    for (int i = 0; i < 4; i++)
        soff[i] = lrow * 128 + (((lcu + i) ^ lr7) << 4);

    auto issue = [&](int buf, int t) {
        const int m0 = (t >> 6) * 128;
        const int n0 = (t & 63) * 128;
        const uint32_t s0 = sb + buf * STAGEB;
        const __half* gA0 = Ahi + (size_t)(m0 + lrow) * 64 + lcol;
        const __half* gA1 = Alo + (size_t)(m0 + lrow) * 64 + lcol;
        const __half* gB0 = Bhi + (size_t)(n0 + lrow) * 64 + lcol;
#pragma unroll
        for (int i = 0; i < 4; i++) {
            cpa16(s0 + 0 * TILEB + soff[i], gA0 + i * 8);
            cpa16(s0 + 1 * TILEB + soff[i], gA1 + i * 8);
            cpa16(s0 + 2 * TILEB + soff[i], gB0 + i * 8);
        }
    };

    const int lane = tid & 31;
    const int wid  = tid >> 5;
    const int wm   = (wid & 3) * 32;
    const int wn   = (wid >> 2) * 64;

    const int a_row = wm + (lane & 15);
    const int a_r7  = a_row & 7;
    const int au    = lane >> 4;
    const int b_row = wn + (lane & 7) + (((lane >> 4) & 1) << 3);
    const int b_r7  = b_row & 7;
    const int bu    = (lane >> 3) & 1;
    const int er = lane >> 2;
    const int ec = (lane & 3) * 2;

    // hoisted per-kc swizzle offsets (thread-constant)
    uint32_t aoffk[4], boffk[4];
#pragma unroll
    for (int kc = 0; kc < 4; kc++) {
        aoffk[kc] = ((((kc << 1) + au) ^ a_r7) << 4);
        boffk[kc] = ((((kc << 1) + bu) ^ b_r7) << 4);
    }
    // per-stage LDSM base addresses
    const uint32_t abase0 = sb + a_row * 128;
    const uint32_t bbase0 = sb + 2 * TILEB + b_row * 128;

    int t0 = blockIdx.x;
    const int stride = gridDim.x;
    if (t0 >= total_tiles) return;

    issue(0, t0);
    asm volatile("cp.async.commit_group;");

    int idx = 0;
    for (int t = t0; t < total_tiles; t += stride, idx++) {
        const int buf = idx & 1;
        const int nt = t + stride;
        if (nt < total_tiles) issue(1 - buf, nt);
        asm volatile("cp.async.commit_group;");
        asm volatile("cp.async.wait_group 1;");
        __syncthreads();

        const uint32_t sbuf = buf ? (uint32_t)STAGEB : 0u;
        const uint32_t abase_row = abase0 + sbuf;
        const uint32_t bbase_row = bbase0 + sbuf;

        float acc[16][4];
#pragma unroll
        for (int i = 0; i < 16; i++)
#pragma unroll
            for (int j = 0; j < 4; j++) acc[i][j] = 0.f;

#pragma unroll
        for (int kc = 0; kc < 4; kc++) {
            uint32_t Ah[8], Al[8], bh[16];
            ldm_x4(Ah[0], Ah[1], Ah[2], Ah[3], abase_row + aoffk[kc]);
            ldm_x4(Ah[4], Ah[5], Ah[6], Ah[7], abase_row + aoffk[kc] + 16 * 128);
            ldm_x4(Al[0], Al[1], Al[2], Al[3], abase_row + TILEB + aoffk[kc]);
            ldm_x4(Al[4], Al[5], Al[6], Al[7], abase_row + TILEB + aoffk[kc] + 16 * 128);
#pragma unroll
            for (int nt2 = 0; nt2 < 4; nt2++)
                ldm_x4(bh[4 * nt2], bh[4 * nt2 + 1], bh[4 * nt2 + 2], bh[4 * nt2 + 3],
                       bbase_row + boffk[kc] + nt2 * 16 * 128);
#pragma unroll
            for (int nt2 = 0; nt2 < 4; nt2++) {
                mma16816(acc[2 * nt2],         Ah,     bh[4 * nt2],     bh[4 * nt2 + 1]);
                mma16816(acc[2 * nt2 + 1],     Ah,     bh[4 * nt2 + 2], bh[4 * nt2 + 3]);
                mma16816(acc[8 + 2 * nt2],     Ah + 4, bh[4 * nt2],     bh[4 * nt2 + 1]);
                mma16816(acc[8 + 2 * nt2 + 1], Ah + 4, bh[4 * nt2 + 2], bh[4 * nt2 + 3]);
            }
#pragma unroll
            for (int nt2 = 0; nt2 < 4; nt2++) {
                mma16816(acc[2 * nt2],         Al,     bh[4 * nt2],     bh[4 * nt2 + 1]);
                mma16816(acc[2 * nt2 + 1],     Al,     bh[4 * nt2 + 2], bh[4 * nt2 + 3]);
                mma16816(acc[8 + 2 * nt2],     Al + 4, bh[4 * nt2],     bh[4 * nt2 + 1]);
                mma16816(acc[8 + 2 * nt2 + 1], Al + 4, bh[4 * nt2 + 2], bh[4 * nt2 + 3]);
            }
        }

        const int m0 = (t >> 6) * 128;
        const int n0 = (t & 63) * 128;
#pragma unroll
        for (int mi = 0; mi < 2; mi++)
#pragma unroll
            for (int ni = 0; ni < 8; ni++) {
                float* f = acc[mi * 8 + ni];
                size_t r = (size_t)(m0 + wm + mi * 16 + er);
                int col = n0 + wn + ni * 8 + ec;
                *(float2*)(C + r * N + col)       = make_float2(f[0], f[1]);
                *(float2*)(C + (r + 8) * N + col) = make_float2(f[2], f[3]);
            }
        __syncthreads();
    }
}

// ---------------- fused edge gather + scatter: 2 edges / 16-lane group ------
__global__ void edge_fused(const float* __restrict__ Z, const float* __restrict__ HW,
                           const int* __restrict__ row, const int* __restrict__ col,
                           const int* __restrict__ et, const float* __restrict__ ev,
                           float* __restrict__ agg, int Ehalf, int N) {
    int gi  = blockIdx.x * blockDim.x + threadIdx.x;
    int e0  = gi >> 4;
    int sub = threadIdx.x & 15;
    if (e0 >= Ehalf) return;
    int e1 = e0 + Ehalf;

    int r0 = row[e0], c0 = col[e0], t0 = et[e0];
    int r1 = row[e1], c1 = col[e1], t1 = et[e1];
    float z0 = Z[(size_t)r0 * N + c0];
    float z1 = Z[(size_t)r1 * N + c1];
    float av0 = z0 * ev[e0];
    float av1 = z1 * ev[e1];
    float4 m0 = ((const float4*)(HW + ((size_t)t0 * N + c0) * 64))[sub];
    float4 m1 = ((const float4*)(HW + ((size_t)t1 * N + c1) * 64))[sub];

    float* d0 = agg + (size_t)r0 * 64 + sub * 4;
    float* d1 = agg + (size_t)r1 * 64 + sub * 4;
    asm volatile("red.global.add.v4.f32 [%0], {%1, %2, %3, %4};"
                 :: "l"(d0), "f"(m0.x * av0), "f"(m0.y * av0),
                    "f"(m0.z * av0), "f"(m0.w * av0) : "memory");
    asm volatile("red.global.add.v4.f32 [%0], {%1, %2, %3, %4};"
                 :: "l"(d1), "f"(m1.x * av1), "f"(m1.y * av1),
                    "f"(m1.z * av1), "f"(m1.w * av1) : "memory");
}

// ---------------------------------------------------------------------------
extern "C" void kernel_launch(void* const* d_in, const int* in_sizes, int n_in,
                              void* d_out, int out_size) {
    const float* x       = (const float*)d_in[0];
    const float* emb     = (const float*)d_in[1];
    const float* bilin   = (const float*)d_in[2];
    const float* eval    = (const float*)d_in[3];
    const float* W_root  = (const float*)d_in[4];
    const float* W_rel   = (const float*)d_in[5];
    const float* bias    = (const float*)d_in[6];
    const float* ln_g    = (const float*)d_in[7];
    const float* ln_b    = (const float*)d_in[8];
    const int*   erow    = (const int*)d_in[9];
    const int*   ecol    = (const int*)d_in[10];
    const int*   etype   = (const int*)d_in[11];

    const int NX = in_sizes[0] / D;
    const int NE = in_sizes[1] / D;
    const int N  = NX + NE;
    const int E  = in_sizes[3];

    float* out   = (float*)d_out;
    float* Hout  = out;
    float* Zbase = out + (size_t)N * D;

    float *H, *HW, *aggA, *aggB;
    uint2 *hbhi, *hblo, *hhi;
    cudaGetSymbolAddress((void**)&H,    g_H);
    cudaGetSymbolAddress((void**)&HW,   g_HW);
    cudaGetSymbolAddress((void**)&aggA, g_aggA);
    cudaGetSymbolAddress((void**)&aggB, g_aggB);
    cudaGetSymbolAddress((void**)&hbhi, g_hbhi);
    cudaGetSymbolAddress((void**)&hblo, g_hblo);
    cudaGetSymbolAddress((void**)&hhi,  g_hhi);

    cudaFuncSetAttribute(zgemm_mma, cudaFuncAttributeMaxDynamicSharedMemorySize, SM_TOT);

    int nsm = 148;
    cudaDeviceGetAttribute(&nsm, cudaDevAttrMultiProcessorCount, 0);

    {
        int total = N * D;
        int blocks = (total / 4 + 255) / 256;
        concat_split<<<blocks, 256>>>(x, emb, H, hhi, NX * D, total);
    }

    const int tiles_n = N / 128;
    const int total_tiles = tiles_n * tiles_n;
    const int zgrid = 2 * nsm;
    dim3 ngrid(N / 32, 5);
    const int Ehalf = E / 2;
    const int edge_blocks = (Ehalf * 16 + 255) / 256;

    const float* ins[3]  = { H, aggA, aggB };
    float*       outs[3] = { aggA, aggB, Hout };

    for (int l = 0; l < 3; l++) {
        float* Zl   = Zbase + (size_t)l * N * N;
        const float* lng = (l == 0) ? nullptr : ln_g + (size_t)(l - 1) * D;
        const float* lnb = (l == 0) ? nullptr : ln_b + (size_t)(l - 1) * D;
        int relu = (l > 0) ? 1 : 0;

        ngemm_all<<<ngrid, 256>>>(ins[l], lng, lnb,
                                  bilin + (size_t)l * D * D,
                                  W_rel + (size_t)l * 3 * D * D,
                                  W_root + (size_t)l * D * D,
                                  bias + (size_t)l * D,
                                  (__half*)hbhi, (__half*)hblo, (__half2*)hhi,
                                  HW, outs[l], relu, N);
        zgemm_mma<<<zgrid, 256, SM_TOT>>>((const __half*)hbhi, (const __half*)hblo,
                                          (const __half*)hhi, Zl, N, total_tiles);
        edge_fused<<<edge_blocks, 256>>>(Zl, HW, erow, ecol, etype, eval,
                                         outs[l], Ehalf, N);
    }
}

// round 10
// speedup vs baseline: 1.2662x; 1.1556x over previous
#include <cuda_runtime.h>
#include <cuda_fp16.h>
#include <cstdint>

// ---------------------------------------------------------------------------
// CTDExplainer: 3-layer relational GCN explainer. N=8192, D=64, R=3, E=262144.
// Round 10: zgemm band-major persistent scheduling — each CTA owns a
// contiguous chunk of tiles within an m-band, so the 32KB A(hi/lo) tile is
// loaded once per band (<=2x per CTA) and only 16KB B streams per tile
// (double-buffered cp.async). 3x less async traffic/issue in the hot loop.
// MMA math bit-identical to rounds 6-9.
// Output layout: [ H (N*64) | z0 (N*N) | z1 | z2 ]  fp32.
// ---------------------------------------------------------------------------

#define MAXN 8192
#define MAXE 262144
#define D 64

__device__ float g_H   [MAXN * D];
__device__ float g_HW  [3 * MAXN * D];
__device__ float g_aggA[MAXN * D];
__device__ float g_aggB[MAXN * D];
__device__ uint2 g_hbhi[MAXN * D / 4];
__device__ uint2 g_hblo[MAXN * D / 4];
__device__ uint2 g_hhi [MAXN * D / 4];

// ---------------- concat x|emb into H (+ fp16 hi for layer-0 B operand) -----
__global__ void concat_split(const float* __restrict__ x, const float* __restrict__ emb,
                             float* __restrict__ H, uint2* __restrict__ hhi,
                             int nx_elems, int total_elems) {
    int i = (blockIdx.x * blockDim.x + threadIdx.x) * 4;
    if (i >= total_elems) return;
    float4 v = (i < nx_elems) ? *(const float4*)(x + i)
                              : *(const float4*)(emb + (i - nx_elems));
    *(float4*)(H + i) = v;
    __half2 h01 = __halves2half2(__float2half_rn(v.x), __float2half_rn(v.y));
    __half2 h23 = __halves2half2(__float2half_rn(v.z), __float2half_rn(v.w));
    uint2 ho;
    ho.x = *(uint32_t*)&h01; ho.y = *(uint32_t*)&h23;
    hhi[i >> 2] = ho;
}

// ---------------- fused per-layer small GEMMs + inline LayerNorm -------------
__global__ void __launch_bounds__(256) ngemm_all(
    const float* __restrict__ In, const float* __restrict__ lng,
    const float* __restrict__ lnb, const float* __restrict__ bilin,
    const float* __restrict__ Wrel, const float* __restrict__ Wroot,
    const float* __restrict__ bias, __half* __restrict__ hbhi,
    __half* __restrict__ hblo, __half2* __restrict__ hhi,
    float* __restrict__ HW, float* __restrict__ agg, int relu, int N) {
    __shared__ float Ws[64][64];
    __shared__ float Is[32][65];
    const int tid  = threadIdx.x;
    const int row0 = blockIdx.x * 32;
    const int o    = blockIdx.y;

    const float* W = (o == 0) ? bilin : (o < 4) ? Wrel + (size_t)(o - 1) * 4096 : Wroot;
    const int act = (o > 0) ? relu : 0;

    for (int i = tid; i < 64 * 64; i += 256) Ws[i >> 6][i & 63] = W[i];
    for (int i = tid; i < 32 * 64; i += 256)
        Is[i >> 6][i & 63] = In[(size_t)(row0 + (i >> 6)) * 64 + (i & 63)];
    __syncthreads();

    const int lrow = tid >> 3;
    const int l8   = tid & 7;
    if (lng) {
        float v[8];
        float s = 0.f, q = 0.f;
#pragma unroll
        for (int j = 0; j < 8; j++) {
            v[j] = Is[lrow][l8 * 8 + j];
            s += v[j]; q += v[j] * v[j];
        }
#pragma unroll
        for (int off = 4; off; off >>= 1) {
            s += __shfl_xor_sync(0xffffffffu, s, off);
            q += __shfl_xor_sync(0xffffffffu, q, off);
        }
        float mu  = s * (1.f / 64.f);
        float inv = rsqrtf(q * (1.f / 64.f) - mu * mu + 1e-5f);
#pragma unroll
        for (int j = 0; j < 8; j++) {
            int c = l8 * 8 + j;
            Is[lrow][c] = (v[j] - mu) * inv * lng[c] + lnb[c];
        }
    }
    if (o == 0) {
        if (lng) {
#pragma unroll
            for (int j = 0; j < 4; j++) {
                int c = l8 * 8 + 2 * j;
                hhi[((size_t)(row0 + lrow) * 64 + c) >> 1] =
                    __halves2half2(__float2half_rn(Is[lrow][c]),
                                   __float2half_rn(Is[lrow][c + 1]));
            }
        }
    } else if (act) {
#pragma unroll
        for (int j = 0; j < 8; j++) {
            int c = l8 * 8 + j;
            Is[lrow][c] = fmaxf(Is[lrow][c], 0.f);
        }
    }
    __syncthreads();

    const int c  = tid & 63;
    const int r0 = tid >> 6;
    float acc[8];
    float bv = (o == 4) ? bias[c] : 0.f;
#pragma unroll
    for (int i = 0; i < 8; i++) acc[i] = bv;
#pragma unroll
    for (int k = 0; k < 64; k++) {
        float w = Ws[k][c];
#pragma unroll
        for (int i = 0; i < 8; i++) acc[i] += Is[r0 + i * 4][k] * w;
    }

    if (o == 0) {
#pragma unroll
        for (int i = 0; i < 8; i++) {
            size_t idx = (size_t)(row0 + r0 + i * 4) * 64 + c;
            __half h = __float2half_rn(acc[i]);
            hbhi[idx] = h;
            hblo[idx] = __float2half_rn(acc[i] - __half2float(h));
        }
    } else if (o < 4) {
        float* Out = HW + (size_t)(o - 1) * N * 64;
#pragma unroll
        for (int i = 0; i < 8; i++)
            Out[(size_t)(row0 + r0 + i * 4) * 64 + c] = acc[i];
    } else {
#pragma unroll
        for (int i = 0; i < 8; i++)
            agg[(size_t)(row0 + r0 + i * 4) * 64 + c] = acc[i];
    }
}

// ---------------- persistent HMMA GEMM: C = (Ahi + Alo) @ Bhi^T -------------
// Band-major tile order (tile = band*64 + n). Each CTA takes a contiguous
// chunk: A(hi/lo) cp.async'd once per band, B double-buffered per tile.
// SMEM: Ahi(16K) | Alo(16K) | B0(16K) | B1(16K) = 64KB, 2 CTA/SM.
#define TILEB 16384
#define SM_TOT (4 * TILEB)

__device__ __forceinline__ uint32_t smem_u32(const void* p) {
    uint32_t a;
    asm("{ .reg .u64 t; cvta.to.shared.u64 t, %1; cvt.u32.u64 %0, t; }" : "=r"(a) : "l"(p));
    return a;
}
__device__ __forceinline__ void ldm_x4(uint32_t& r0, uint32_t& r1, uint32_t& r2,
                                       uint32_t& r3, uint32_t addr) {
    asm volatile("ldmatrix.sync.aligned.m8n8.x4.shared.b16 {%0,%1,%2,%3}, [%4];"
                 : "=r"(r0), "=r"(r1), "=r"(r2), "=r"(r3) : "r"(addr));
}
__device__ __forceinline__ void mma16816(float* c, const uint32_t* a,
                                         uint32_t b0, uint32_t b1) {
    asm volatile(
        "mma.sync.aligned.m16n8k16.row.col.f32.f16.f16.f32 "
        "{%0,%1,%2,%3}, {%4,%5,%6,%7}, {%8,%9}, {%0,%1,%2,%3};"
        : "+f"(c[0]), "+f"(c[1]), "+f"(c[2]), "+f"(c[3])
        : "r"(a[0]), "r"(a[1]), "r"(a[2]), "r"(a[3]), "r"(b0), "r"(b1));
}
__device__ __forceinline__ void cpa16(uint32_t saddr, const void* gaddr) {
    asm volatile("cp.async.cg.shared.global [%0], [%1], 16;"
                 :: "r"(saddr), "l"(gaddr));
}

__global__ void __launch_bounds__(256, 2) zgemm_mma(
    const __half* __restrict__ Ahi, const __half* __restrict__ Alo,
    const __half* __restrict__ Bhi, float* __restrict__ C, int N,
    int total_tiles) {
    extern __shared__ __align__(16) char smem[];
    const int tid = threadIdx.x;
    const uint32_t sb = smem_u32(smem);

    // per-thread cp.async slots (tile-invariant)
    const int lrow = tid >> 1;
    const int lcu  = (tid & 1) * 4;
    const int lr7  = lrow & 7;
    const int lcol = (tid & 1) * 32;
    uint32_t soff[4];
#pragma unroll
    for (int i = 0; i < 4; i++)
        soff[i] = lrow * 128 + (((lcu + i) ^ lr7) << 4);

    auto loadA = [&](int band) {
        const __half* gA0 = Ahi + (size_t)(band * 128 + lrow) * 64 + lcol;
        const __half* gA1 = Alo + (size_t)(band * 128 + lrow) * 64 + lcol;
#pragma unroll
        for (int i = 0; i < 4; i++) {
            cpa16(sb + 0 * TILEB + soff[i], gA0 + i * 8);
            cpa16(sb + 1 * TILEB + soff[i], gA1 + i * 8);
        }
    };
    auto issueB = [&](int buf, int n0) {
        const __half* gB = Bhi + (size_t)(n0 * 128 + lrow) * 64 + lcol;
        const uint32_t s0 = sb + 2 * TILEB + buf * TILEB;
#pragma unroll
        for (int i = 0; i < 4; i++)
            cpa16(s0 + soff[i], gB + i * 8);
    };

    const int lane = tid & 31;
    const int wid  = tid >> 5;
    const int wm   = (wid & 3) * 32;
    const int wn   = (wid >> 2) * 64;

    const int a_row = wm + (lane & 15);
    const int a_r7  = a_row & 7;
    const int au    = lane >> 4;
    const int b_row = wn + (lane & 7) + (((lane >> 4) & 1) << 3);
    const int b_r7  = b_row & 7;
    const int bu    = (lane >> 3) & 1;
    const int er = lane >> 2;
    const int ec = (lane & 3) * 2;

    uint32_t aoffk[4], boffk[4];
#pragma unroll
    for (int kc = 0; kc < 4; kc++) {
        aoffk[kc] = ((((kc << 1) + au) ^ a_r7) << 4);
        boffk[kc] = ((((kc << 1) + bu) ^ b_r7) << 4);
    }
    const uint32_t abase_row = sb + a_row * 128;
    const uint32_t bbase0    = sb + 2 * TILEB + b_row * 128;

    const int G = gridDim.x;
    const int p = blockIdx.x;
    const int start = (int)(((long long)p * total_tiles) / G);
    const int end   = (int)(((long long)(p + 1) * total_tiles) / G);
    if (start >= end) return;

    int curBand = start >> 6;
    loadA(curBand);
    issueB(0, start & 63);
    asm volatile("cp.async.commit_group;");

    int idx = 0;
    for (int t = start; t < end; t++, idx++) {
        const int band = t >> 6;
        if (band != curBand) {
            // previous tile's compute fully done (trailing sync); safe to
            // overwrite A region. Own commit group so wait_group 1 drains it.
            loadA(band);
            asm volatile("cp.async.commit_group;");
            curBand = band;
        }
        const int buf = idx & 1;
        if (t + 1 < end) issueB(1 - buf, (t + 1) & 63);
        asm volatile("cp.async.commit_group;");
        asm volatile("cp.async.wait_group 1;");
        __syncthreads();

        const uint32_t bbase_row = bbase0 + (buf ? (uint32_t)TILEB : 0u);

        float acc[16][4];
#pragma unroll
        for (int i = 0; i < 16; i++)
#pragma unroll
            for (int j = 0; j < 4; j++) acc[i][j] = 0.f;

#pragma unroll
        for (int kc = 0; kc < 4; kc++) {
            uint32_t Ah[8], Al[8], bh[16];
            ldm_x4(Ah[0], Ah[1], Ah[2], Ah[3], abase_row + aoffk[kc]);
            ldm_x4(Ah[4], Ah[5], Ah[6], Ah[7], abase_row + aoffk[kc] + 16 * 128);
            ldm_x4(Al[0], Al[1], Al[2], Al[3], abase_row + TILEB + aoffk[kc]);
            ldm_x4(Al[4], Al[5], Al[6], Al[7], abase_row + TILEB + aoffk[kc] + 16 * 128);
#pragma unroll
            for (int nt2 = 0; nt2 < 4; nt2++)
                ldm_x4(bh[4 * nt2], bh[4 * nt2 + 1], bh[4 * nt2 + 2], bh[4 * nt2 + 3],
                       bbase_row + boffk[kc] + nt2 * 16 * 128);
#pragma unroll
            for (int nt2 = 0; nt2 < 4; nt2++) {
                mma16816(acc[2 * nt2],         Ah,     bh[4 * nt2],     bh[4 * nt2 + 1]);
                mma16816(acc[2 * nt2 + 1],     Ah,     bh[4 * nt2 + 2], bh[4 * nt2 + 3]);
                mma16816(acc[8 + 2 * nt2],     Ah + 4, bh[4 * nt2],     bh[4 * nt2 + 1]);
                mma16816(acc[8 + 2 * nt2 + 1], Ah + 4, bh[4 * nt2 + 2], bh[4 * nt2 + 3]);
            }
#pragma unroll
            for (int nt2 = 0; nt2 < 4; nt2++) {
                mma16816(acc[2 * nt2],         Al,     bh[4 * nt2],     bh[4 * nt2 + 1]);
                mma16816(acc[2 * nt2 + 1],     Al,     bh[4 * nt2 + 2], bh[4 * nt2 + 3]);
                mma16816(acc[8 + 2 * nt2],     Al + 4, bh[4 * nt2],     bh[4 * nt2 + 1]);
                mma16816(acc[8 + 2 * nt2 + 1], Al + 4, bh[4 * nt2 + 2], bh[4 * nt2 + 3]);
            }
        }

        const int m0 = band * 128;
        const int n0 = (t & 63) * 128;
#pragma unroll
        for (int mi = 0; mi < 2; mi++)
#pragma unroll
            for (int ni = 0; ni < 8; ni++) {
                float* f = acc[mi * 8 + ni];
                size_t r = (size_t)(m0 + wm + mi * 16 + er);
                int col = n0 + wn + ni * 8 + ec;
                *(float2*)(C + r * N + col)       = make_float2(f[0], f[1]);
                *(float2*)(C + (r + 8) * N + col) = make_float2(f[2], f[3]);
            }
        __syncthreads();
    }
}

// ---------------- fused edge gather + scatter: 2 edges / 16-lane group ------
__global__ void edge_fused(const float* __restrict__ Z, const float* __restrict__ HW,
                           const int* __restrict__ row, const int* __restrict__ col,
                           const int* __restrict__ et, const float* __restrict__ ev,
                           float* __restrict__ agg, int Ehalf, int N) {
    int gi  = blockIdx.x * blockDim.x + threadIdx.x;
    int e0  = gi >> 4;
    int sub = threadIdx.x & 15;
    if (e0 >= Ehalf) return;
    int e1 = e0 + Ehalf;

    int r0 = row[e0], c0 = col[e0], t0 = et[e0];
    int r1 = row[e1], c1 = col[e1], t1 = et[e1];
    float z0 = Z[(size_t)r0 * N + c0];
    float z1 = Z[(size_t)r1 * N + c1];
    float av0 = z0 * ev[e0];
    float av1 = z1 * ev[e1];
    float4 m0 = ((const float4*)(HW + ((size_t)t0 * N + c0) * 64))[sub];
    float4 m1 = ((const float4*)(HW + ((size_t)t1 * N + c1) * 64))[sub];

    float* d0 = agg + (size_t)r0 * 64 + sub * 4;
    float* d1 = agg + (size_t)r1 * 64 + sub * 4;
    asm volatile("red.global.add.v4.f32 [%0], {%1, %2, %3, %4};"
                 :: "l"(d0), "f"(m0.x * av0), "f"(m0.y * av0),
                    "f"(m0.z * av0), "f"(m0.w * av0) : "memory");
    asm volatile("red.global.add.v4.f32 [%0], {%1, %2, %3, %4};"
                 :: "l"(d1), "f"(m1.x * av1), "f"(m1.y * av1),
                    "f"(m1.z * av1), "f"(m1.w * av1) : "memory");
}

// ---------------------------------------------------------------------------
extern "C" void kernel_launch(void* const* d_in, const int* in_sizes, int n_in,
                              void* d_out, int out_size) {
    const float* x       = (const float*)d_in[0];
    const float* emb     = (const float*)d_in[1];
    const float* bilin   = (const float*)d_in[2];
    const float* eval    = (const float*)d_in[3];
    const float* W_root  = (const float*)d_in[4];
    const float* W_rel   = (const float*)d_in[5];
    const float* bias    = (const float*)d_in[6];
    const float* ln_g    = (const float*)d_in[7];
    const float* ln_b    = (const float*)d_in[8];
    const int*   erow    = (const int*)d_in[9];
    const int*   ecol    = (const int*)d_in[10];
    const int*   etype   = (const int*)d_in[11];

    const int NX = in_sizes[0] / D;
    const int NE = in_sizes[1] / D;
    const int N  = NX + NE;
    const int E  = in_sizes[3];

    float* out   = (float*)d_out;
    float* Hout  = out;
    float* Zbase = out + (size_t)N * D;

    float *H, *HW, *aggA, *aggB;
    uint2 *hbhi, *hblo, *hhi;
    cudaGetSymbolAddress((void**)&H,    g_H);
    cudaGetSymbolAddress((void**)&HW,   g_HW);
    cudaGetSymbolAddress((void**)&aggA, g_aggA);
    cudaGetSymbolAddress((void**)&aggB, g_aggB);
    cudaGetSymbolAddress((void**)&hbhi, g_hbhi);
    cudaGetSymbolAddress((void**)&hblo, g_hblo);
    cudaGetSymbolAddress((void**)&hhi,  g_hhi);

    cudaFuncSetAttribute(zgemm_mma, cudaFuncAttributeMaxDynamicSharedMemorySize, SM_TOT);

    int nsm = 148;
    cudaDeviceGetAttribute(&nsm, cudaDevAttrMultiProcessorCount, 0);

    {
        int total = N * D;
        int blocks = (total / 4 + 255) / 256;
        concat_split<<<blocks, 256>>>(x, emb, H, hhi, NX * D, total);
    }

    const int tiles_n = N / 128;
    const int total_tiles = tiles_n * tiles_n;
    const int zgrid = 2 * nsm;
    dim3 ngrid(N / 32, 5);
    const int Ehalf = E / 2;
    const int edge_blocks = (Ehalf * 16 + 255) / 256;

    const float* ins[3]  = { H, aggA, aggB };
    float*       outs[3] = { aggA, aggB, Hout };

    for (int l = 0; l < 3; l++) {
        float* Zl   = Zbase + (size_t)l * N * N;
        const float* lng = (l == 0) ? nullptr : ln_g + (size_t)(l - 1) * D;
        const float* lnb = (l == 0) ? nullptr : ln_b + (size_t)(l - 1) * D;
        int relu = (l > 0) ? 1 : 0;

        ngemm_all<<<ngrid, 256>>>(ins[l], lng, lnb,
                                  bilin + (size_t)l * D * D,
                                  W_rel + (size_t)l * 3 * D * D,
                                  W_root + (size_t)l * D * D,
                                  bias + (size_t)l * D,
                                  (__half*)hbhi, (__half*)hblo, (__half2*)hhi,
                                  HW, outs[l], relu, N);
        zgemm_mma<<<zgrid, 256, SM_TOT>>>((const __half*)hbhi, (const __half*)hblo,
                                          (const __half*)hhi, Zl, N, total_tiles);
        edge_fused<<<edge_blocks, 256>>>(Zl, HW, erow, ecol, etype, eval,
                                         outs[l], Ehalf, N);
    }
}

// round 11
// speedup vs baseline: 1.4821x; 1.1706x over previous
#include <cuda_runtime.h>
#include <cuda_fp16.h>
#include <cstdint>

// ---------------------------------------------------------------------------
// CTDExplainer: 3-layer relational GCN explainer. N=8192, D=64, R=3, E=262144.
// Round 11: small per-layer GEMMs moved to HMMA (3-term fp16 hi/lo, ~fp32
// accuracy), LN/relu/concat folded into the staging path (concat kernel and
// g_H eliminated). zgemm (at its legacy-HMMA floor) and edge_fused unchanged.
// Output layout: [ H (N*64) | z0 (N*N) | z1 | z2 ]  fp32.
// ---------------------------------------------------------------------------

#define MAXN 8192
#define MAXE 262144
#define D 64

__device__ float g_HW  [3 * MAXN * D];
__device__ float g_aggA[MAXN * D];
__device__ float g_aggB[MAXN * D];
__device__ uint2 g_hbhi[MAXN * D / 4];
__device__ uint2 g_hblo[MAXN * D / 4];
__device__ uint2 g_hhi [MAXN * D / 4];

__device__ __forceinline__ uint32_t smem_u32(const void* p) {
    uint32_t a;
    asm("{ .reg .u64 t; cvta.to.shared.u64 t, %1; cvt.u32.u64 %0, t; }" : "=r"(a) : "l"(p));
    return a;
}
__device__ __forceinline__ void ldm_x4(uint32_t& r0, uint32_t& r1, uint32_t& r2,
                                       uint32_t& r3, uint32_t addr) {
    asm volatile("ldmatrix.sync.aligned.m8n8.x4.shared.b16 {%0,%1,%2,%3}, [%4];"
                 : "=r"(r0), "=r"(r1), "=r"(r2), "=r"(r3) : "r"(addr));
}
__device__ __forceinline__ void mma16816(float* c, const uint32_t* a,
                                         uint32_t b0, uint32_t b1) {
    asm volatile(
        "mma.sync.aligned.m16n8k16.row.col.f32.f16.f16.f32 "
        "{%0,%1,%2,%3}, {%4,%5,%6,%7}, {%8,%9}, {%0,%1,%2,%3};"
        : "+f"(c[0]), "+f"(c[1]), "+f"(c[2]), "+f"(c[3])
        : "r"(a[0]), "r"(a[1]), "r"(a[2]), "r"(a[3]), "r"(b0), "r"(b1));
}
__device__ __forceinline__ void cpa16(uint32_t saddr, const void* gaddr) {
    asm volatile("cp.async.cg.shared.global [%0], [%1], 16;"
                 :: "r"(saddr), "l"(gaddr));
}

// ---------------- HMMA per-layer small GEMMs (LN/relu/concat fused) ---------
// grid = (N/128, 5). blockIdx.y selects:
//   0: Hb = base(In) @ bilin -> hbhi/hblo; also exports hhi = fp16(base(In))
//   1..3: HW[y-1] = act(In) @ W_rel[y-1]
//   4: agg = act(In) @ W_root + bias
// base(In) = LN(In) for layers>0 (lng != null), raw for layer 0.
// In rows come from inA, or inB for rows >= nxrows (layer-0 concat).
// 3 fp16 terms: Ihi*Whi + Ilo*Whi + Ihi*Wlo  (error ~2^-22).
#define NG_IHI 0
#define NG_ILO 16384
#define NG_WHI 32768
#define NG_WLO 40960
#define NG_TOT 49152

__global__ void __launch_bounds__(256) ngemm_mma(
    const float* __restrict__ inA, const float* __restrict__ inB, int nxrows,
    const float* __restrict__ lng, const float* __restrict__ lnb,
    const float* __restrict__ bilin, const float* __restrict__ Wrel,
    const float* __restrict__ Wroot, const float* __restrict__ bias,
    __half2* __restrict__ hbhi, __half2* __restrict__ hblo,
    __half2* __restrict__ hhi, float* __restrict__ HW,
    float* __restrict__ agg, int relu, int N) {
    extern __shared__ __align__(16) char smem[];
    const int tid  = threadIdx.x;
    const int row0 = blockIdx.x * 128;
    const int o    = blockIdx.y;
    const uint32_t sb = smem_u32(smem);

    const float* W = (o == 0) ? bilin : (o < 4) ? Wrel + (size_t)(o - 1) * 4096 : Wroot;
    const int act = (o > 0) ? relu : 0;

    // stage W transposed (Wt[n][k]) as fp16 hi/lo, swizzled
    for (int idx = tid; idx < 4096; idx += 256) {
        int k = idx >> 6, n = idx & 63;
        float w = W[idx];
        __half h = __float2half_rn(w);
        __half l = __float2half_rn(w - __half2float(h));
        uint32_t unit = (uint32_t)(k >> 3) ^ (uint32_t)(n & 7);
        uint32_t byte = n * 128 + unit * 16 + (k & 7) * 2;
        *(__half*)(smem + NG_WHI + byte) = h;
        *(__half*)(smem + NG_WLO + byte) = l;
    }

    // stage 128 input rows: LN / act / exports, fp16 hi/lo swizzled
    {
        const int r    = tid >> 1;
        const int hlf  = tid & 1;
        const int gr   = row0 + r;
        const float* src = (inB && gr >= nxrows)
                         ? (inB + (size_t)(gr - nxrows) * 64 + hlf * 32)
                         : (inA + (size_t)gr * 64 + hlf * 32);
        float v[32];
#pragma unroll
        for (int i = 0; i < 8; i++) {
            float4 t = *(const float4*)(src + i * 4);
            v[i*4+0] = t.x; v[i*4+1] = t.y; v[i*4+2] = t.z; v[i*4+3] = t.w;
        }
        if (lng) {
            float s = 0.f, q = 0.f;
#pragma unroll
            for (int i = 0; i < 32; i++) { s += v[i]; q += v[i] * v[i]; }
            s += __shfl_xor_sync(0xffffffffu, s, 1);
            q += __shfl_xor_sync(0xffffffffu, q, 1);
            float mu  = s * (1.f / 64.f);
            float inv = rsqrtf(q * (1.f / 64.f) - mu * mu + 1e-5f);
#pragma unroll
            for (int i = 0; i < 32; i++) {
                int c = hlf * 32 + i;
                v[i] = (v[i] - mu) * inv * lng[c] + lnb[c];
            }
        }
        if (o == 0) {
            __half2* dst = hhi + ((size_t)gr * 64 + hlf * 32) / 2;
#pragma unroll
            for (int i = 0; i < 16; i++)
                dst[i] = __halves2half2(__float2half_rn(v[2*i]),
                                        __float2half_rn(v[2*i+1]));
        } else if (act) {
#pragma unroll
            for (int i = 0; i < 32; i++) v[i] = fmaxf(v[i], 0.f);
        }
        const int r7 = r & 7;
#pragma unroll
        for (int u = 0; u < 4; u++) {
            __half hs[8], ls[8];
#pragma unroll
            for (int j = 0; j < 8; j++) {
                float x = v[u * 8 + j];
                __half h = __float2half_rn(x);
                hs[j] = h;
                ls[j] = __float2half_rn(x - __half2float(h));
            }
            uint32_t unit = (uint32_t)(hlf * 4 + u) ^ (uint32_t)r7;
            uint32_t byte = r * 128 + unit * 16;
            *(uint4*)(smem + NG_IHI + byte) = *(uint4*)hs;
            *(uint4*)(smem + NG_ILO + byte) = *(uint4*)ls;
        }
    }
    __syncthreads();

    // MMA: warp w handles rows wm..wm+15, full n=64
    const int lane = tid & 31;
    const int wid  = tid >> 5;
    const int wm   = wid * 16;
    const int a_row = wm + (lane & 15);
    const int a_r7  = a_row & 7;
    const int au    = lane >> 4;
    const int b_row = (lane & 7) + (((lane >> 4) & 1) << 3);
    const int b_r7  = b_row & 7;
    const int bu    = (lane >> 3) & 1;

    const uint32_t ahib = sb + NG_IHI + a_row * 128;
    const uint32_t alob = sb + NG_ILO + a_row * 128;
    const uint32_t whib = sb + NG_WHI + b_row * 128;
    const uint32_t wlob = sb + NG_WLO + b_row * 128;

    float acc[8][4];
#pragma unroll
    for (int i = 0; i < 8; i++)
#pragma unroll
        for (int j = 0; j < 4; j++) acc[i][j] = 0.f;

#pragma unroll
    for (int kc = 0; kc < 4; kc++) {
        const uint32_t aoff = ((((kc << 1) + au) ^ a_r7) << 4);
        const uint32_t boff = ((((kc << 1) + bu) ^ b_r7) << 4);
        uint32_t Ah[4], Al[4], bh[16], bl[16];
        ldm_x4(Ah[0], Ah[1], Ah[2], Ah[3], ahib + aoff);
        ldm_x4(Al[0], Al[1], Al[2], Al[3], alob + aoff);
#pragma unroll
        for (int nt = 0; nt < 4; nt++) {
            ldm_x4(bh[4*nt], bh[4*nt+1], bh[4*nt+2], bh[4*nt+3],
                   whib + boff + nt * 16 * 128);
            ldm_x4(bl[4*nt], bl[4*nt+1], bl[4*nt+2], bl[4*nt+3],
                   wlob + boff + nt * 16 * 128);
        }
#pragma unroll
        for (int ni = 0; ni < 8; ni++) {
            const int bi = (ni >> 1) * 4 + (ni & 1) * 2;
            mma16816(acc[ni], Ah, bh[bi], bh[bi + 1]);
        }
#pragma unroll
        for (int ni = 0; ni < 8; ni++) {
            const int bi = (ni >> 1) * 4 + (ni & 1) * 2;
            mma16816(acc[ni], Al, bh[bi], bh[bi + 1]);
        }
#pragma unroll
        for (int ni = 0; ni < 8; ni++) {
            const int bi = (ni >> 1) * 4 + (ni & 1) * 2;
            mma16816(acc[ni], Ah, bl[bi], bl[bi + 1]);
        }
    }

    // epilogue
    const int er = lane >> 2;
    const int ec = (lane & 3) * 2;
    const int gr = row0 + wm + er;
    if (o == 0) {
#pragma unroll
        for (int ni = 0; ni < 8; ni++) {
            float* f = acc[ni];
            int col = ni * 8 + ec;
            size_t i0 = ((size_t)gr * 64 + col) / 2;
            size_t i1 = ((size_t)(gr + 8) * 64 + col) / 2;
            __half h0 = __float2half_rn(f[0]), h1 = __float2half_rn(f[1]);
            __half h2 = __float2half_rn(f[2]), h3 = __float2half_rn(f[3]);
            hbhi[i0] = __halves2half2(h0, h1);
            hbhi[i1] = __halves2half2(h2, h3);
            hblo[i0] = __halves2half2(__float2half_rn(f[0] - __half2float(h0)),
                                      __float2half_rn(f[1] - __half2float(h1)));
            hblo[i1] = __halves2half2(__float2half_rn(f[2] - __half2float(h2)),
                                      __float2half_rn(f[3] - __half2float(h3)));
        }
    } else if (o < 4) {
        float* Out = HW + (size_t)(o - 1) * N * 64;
#pragma unroll
        for (int ni = 0; ni < 8; ni++) {
            float* f = acc[ni];
            int col = ni * 8 + ec;
            *(float2*)(Out + (size_t)gr * 64 + col)       = make_float2(f[0], f[1]);
            *(float2*)(Out + (size_t)(gr + 8) * 64 + col) = make_float2(f[2], f[3]);
        }
    } else {
#pragma unroll
        for (int ni = 0; ni < 8; ni++) {
            float* f = acc[ni];
            int col = ni * 8 + ec;
            float b0 = bias[col], b1 = bias[col + 1];
            *(float2*)(agg + (size_t)gr * 64 + col)       = make_float2(f[0] + b0, f[1] + b1);
            *(float2*)(agg + (size_t)(gr + 8) * 64 + col) = make_float2(f[2] + b0, f[3] + b1);
        }
    }
}

// ---------------- persistent HMMA GEMM: C = (Ahi + Alo) @ Bhi^T -------------
// Band-major tile order; A loaded once per band, B double-buffered cp.async.
#define TILEB 16384
#define SM_TOT (4 * TILEB)

__global__ void __launch_bounds__(256, 2) zgemm_mma(
    const __half* __restrict__ Ahi, const __half* __restrict__ Alo,
    const __half* __restrict__ Bhi, float* __restrict__ C, int N,
    int total_tiles) {
    extern __shared__ __align__(16) char smem[];
    const int tid = threadIdx.x;
    const uint32_t sb = smem_u32(smem);

    const int lrow = tid >> 1;
    const int lcu  = (tid & 1) * 4;
    const int lr7  = lrow & 7;
    const int lcol = (tid & 1) * 32;
    uint32_t soff[4];
#pragma unroll
    for (int i = 0; i < 4; i++)
        soff[i] = lrow * 128 + (((lcu + i) ^ lr7) << 4);

    auto loadA = [&](int band) {
        const __half* gA0 = Ahi + (size_t)(band * 128 + lrow) * 64 + lcol;
        const __half* gA1 = Alo + (size_t)(band * 128 + lrow) * 64 + lcol;
#pragma unroll
        for (int i = 0; i < 4; i++) {
            cpa16(sb + 0 * TILEB + soff[i], gA0 + i * 8);
            cpa16(sb + 1 * TILEB + soff[i], gA1 + i * 8);
        }
    };
    auto issueB = [&](int buf, int n0) {
        const __half* gB = Bhi + (size_t)(n0 * 128 + lrow) * 64 + lcol;
        const uint32_t s0 = sb + 2 * TILEB + buf * TILEB;
#pragma unroll
        for (int i = 0; i < 4; i++)
            cpa16(s0 + soff[i], gB + i * 8);
    };

    const int lane = tid & 31;
    const int wid  = tid >> 5;
    const int wm   = (wid & 3) * 32;
    const int wn   = (wid >> 2) * 64;

    const int a_row = wm + (lane & 15);
    const int a_r7  = a_row & 7;
    const int au    = lane >> 4;
    const int b_row = wn + (lane & 7) + (((lane >> 4) & 1) << 3);
    const int b_r7  = b_row & 7;
    const int bu    = (lane >> 3) & 1;
    const int er = lane >> 2;
    const int ec = (lane & 3) * 2;

    uint32_t aoffk[4], boffk[4];
#pragma unroll
    for (int kc = 0; kc < 4; kc++) {
        aoffk[kc] = ((((kc << 1) + au) ^ a_r7) << 4);
        boffk[kc] = ((((kc << 1) + bu) ^ b_r7) << 4);
    }
    const uint32_t abase_row = sb + a_row * 128;
    const uint32_t bbase0    = sb + 2 * TILEB + b_row * 128;

    const int G = gridDim.x;
    const int p = blockIdx.x;
    const int start = (int)(((long long)p * total_tiles) / G);
    const int end   = (int)(((long long)(p + 1) * total_tiles) / G);
    if (start >= end) return;

    int curBand = start >> 6;
    loadA(curBand);
    issueB(0, start & 63);
    asm volatile("cp.async.commit_group;");

    int idx = 0;
    for (int t = start; t < end; t++, idx++) {
        const int band = t >> 6;
        if (band != curBand) {
            loadA(band);
            asm volatile("cp.async.commit_group;");
            curBand = band;
        }
        const int buf = idx & 1;
        if (t + 1 < end) issueB(1 - buf, (t + 1) & 63);
        asm volatile("cp.async.commit_group;");
        asm volatile("cp.async.wait_group 1;");
        __syncthreads();

        const uint32_t bbase_row = bbase0 + (buf ? (uint32_t)TILEB : 0u);

        float acc[16][4];
#pragma unroll
        for (int i = 0; i < 16; i++)
#pragma unroll
            for (int j = 0; j < 4; j++) acc[i][j] = 0.f;

#pragma unroll
        for (int kc = 0; kc < 4; kc++) {
            uint32_t Ah[8], Al[8], bh[16];
            ldm_x4(Ah[0], Ah[1], Ah[2], Ah[3], abase_row + aoffk[kc]);
            ldm_x4(Ah[4], Ah[5], Ah[6], Ah[7], abase_row + aoffk[kc] + 16 * 128);
            ldm_x4(Al[0], Al[1], Al[2], Al[3], abase_row + TILEB + aoffk[kc]);
            ldm_x4(Al[4], Al[5], Al[6], Al[7], abase_row + TILEB + aoffk[kc] + 16 * 128);
#pragma unroll
            for (int nt2 = 0; nt2 < 4; nt2++)
                ldm_x4(bh[4 * nt2], bh[4 * nt2 + 1], bh[4 * nt2 + 2], bh[4 * nt2 + 3],
                       bbase_row + boffk[kc] + nt2 * 16 * 128);
#pragma unroll
            for (int nt2 = 0; nt2 < 4; nt2++) {
                mma16816(acc[2 * nt2],         Ah,     bh[4 * nt2],     bh[4 * nt2 + 1]);
                mma16816(acc[2 * nt2 + 1],     Ah,     bh[4 * nt2 + 2], bh[4 * nt2 + 3]);
                mma16816(acc[8 + 2 * nt2],     Ah + 4, bh[4 * nt2],     bh[4 * nt2 + 1]);
                mma16816(acc[8 + 2 * nt2 + 1], Ah + 4, bh[4 * nt2 + 2], bh[4 * nt2 + 3]);
            }
#pragma unroll
            for (int nt2 = 0; nt2 < 4; nt2++) {
                mma16816(acc[2 * nt2],         Al,     bh[4 * nt2],     bh[4 * nt2 + 1]);
                mma16816(acc[2 * nt2 + 1],     Al,     bh[4 * nt2 + 2], bh[4 * nt2 + 3]);
                mma16816(acc[8 + 2 * nt2],     Al + 4, bh[4 * nt2],     bh[4 * nt2 + 1]);
                mma16816(acc[8 + 2 * nt2 + 1], Al + 4, bh[4 * nt2 + 2], bh[4 * nt2 + 3]);
            }
        }

        const int m0 = band * 128;
        const int n0 = (t & 63) * 128;
#pragma unroll
        for (int mi = 0; mi < 2; mi++)
#pragma unroll
            for (int ni = 0; ni < 8; ni++) {
                float* f = acc[mi * 8 + ni];
                size_t r = (size_t)(m0 + wm + mi * 16 + er);
                int col = n0 + wn + ni * 8 + ec;
                *(float2*)(C + r * N + col)       = make_float2(f[0], f[1]);
                *(float2*)(C + (r + 8) * N + col) = make_float2(f[2], f[3]);
            }
        __syncthreads();
    }
}

// ---------------- fused edge gather + scatter: 2 edges / 16-lane group ------
__global__ void edge_fused(const float* __restrict__ Z, const float* __restrict__ HW,
                           const int* __restrict__ row, const int* __restrict__ col,
                           const int* __restrict__ et, const float* __restrict__ ev,
                           float* __restrict__ agg, int Ehalf, int N) {
    int gi  = blockIdx.x * blockDim.x + threadIdx.x;
    int e0  = gi >> 4;
    int sub = threadIdx.x & 15;
    if (e0 >= Ehalf) return;
    int e1 = e0 + Ehalf;

    int r0 = row[e0], c0 = col[e0], t0 = et[e0];
    int r1 = row[e1], c1 = col[e1], t1 = et[e1];
    float z0 = Z[(size_t)r0 * N + c0];
    float z1 = Z[(size_t)r1 * N + c1];
    float av0 = z0 * ev[e0];
    float av1 = z1 * ev[e1];
    float4 m0 = ((const float4*)(HW + ((size_t)t0 * N + c0) * 64))[sub];
    float4 m1 = ((const float4*)(HW + ((size_t)t1 * N + c1) * 64))[sub];

    float* d0 = agg + (size_t)r0 * 64 + sub * 4;
    float* d1 = agg + (size_t)r1 * 64 + sub * 4;
    asm volatile("red.global.add.v4.f32 [%0], {%1, %2, %3, %4};"
                 :: "l"(d0), "f"(m0.x * av0), "f"(m0.y * av0),
                    "f"(m0.z * av0), "f"(m0.w * av0) : "memory");
    asm volatile("red.global.add.v4.f32 [%0], {%1, %2, %3, %4};"
                 :: "l"(d1), "f"(m1.x * av1), "f"(m1.y * av1),
                    "f"(m1.z * av1), "f"(m1.w * av1) : "memory");
}

// ---------------------------------------------------------------------------
extern "C" void kernel_launch(void* const* d_in, const int* in_sizes, int n_in,
                              void* d_out, int out_size) {
    const float* x       = (const float*)d_in[0];
    const float* emb     = (const float*)d_in[1];
    const float* bilin   = (const float*)d_in[2];
    const float* eval    = (const float*)d_in[3];
    const float* W_root  = (const float*)d_in[4];
    const float* W_rel   = (const float*)d_in[5];
    const float* bias    = (const float*)d_in[6];
    const float* ln_g    = (const float*)d_in[7];
    const float* ln_b    = (const float*)d_in[8];
    const int*   erow    = (const int*)d_in[9];
    const int*   ecol    = (const int*)d_in[10];
    const int*   etype   = (const int*)d_in[11];

    const int NX = in_sizes[0] / D;
    const int NE = in_sizes[1] / D;
    const int N  = NX + NE;
    const int E  = in_sizes[3];

    float* out   = (float*)d_out;
    float* Hout  = out;
    float* Zbase = out + (size_t)N * D;

    float *HW, *aggA, *aggB;
    uint2 *hbhi, *hblo, *hhi;
    cudaGetSymbolAddress((void**)&HW,   g_HW);
    cudaGetSymbolAddress((void**)&aggA, g_aggA);
    cudaGetSymbolAddress((void**)&aggB, g_aggB);
    cudaGetSymbolAddress((void**)&hbhi, g_hbhi);
    cudaGetSymbolAddress((void**)&hblo, g_hblo);
    cudaGetSymbolAddress((void**)&hhi,  g_hhi);

    cudaFuncSetAttribute(zgemm_mma, cudaFuncAttributeMaxDynamicSharedMemorySize, SM_TOT);
    cudaFuncSetAttribute(ngemm_mma, cudaFuncAttributeMaxDynamicSharedMemorySize, NG_TOT);

    int nsm = 148;
    cudaDeviceGetAttribute(&nsm, cudaDevAttrMultiProcessorCount, 0);

    const int tiles_n = N / 128;
    const int total_tiles = tiles_n * tiles_n;
    const int zgrid = 2 * nsm;
    dim3 ngrid(N / 128, 5);
    const int Ehalf = E / 2;
    const int edge_blocks = (Ehalf * 16 + 255) / 256;

    const float* insA[3] = { x, aggA, aggB };
    const float* insB[3] = { emb, nullptr, nullptr };
    float*       outs[3] = { aggA, aggB, Hout };

    for (int l = 0; l < 3; l++) {
        float* Zl   = Zbase + (size_t)l * N * N;
        const float* lng = (l == 0) ? nullptr : ln_g + (size_t)(l - 1) * D;
        const float* lnb = (l == 0) ? nullptr : ln_b + (size_t)(l - 1) * D;
        int relu = (l > 0) ? 1 : 0;

        ngemm_mma<<<ngrid, 256, NG_TOT>>>(insA[l], insB[l], NX, lng, lnb,
                                          bilin + (size_t)l * D * D,
                                          W_rel + (size_t)l * 3 * D * D,
                                          W_root + (size_t)l * D * D,
                                          bias + (size_t)l * D,
                                          (__half2*)hbhi, (__half2*)hblo,
                                          (__half2*)hhi, HW, outs[l], relu, N);
        zgemm_mma<<<zgrid, 256, SM_TOT>>>((const __half*)hbhi, (const __half*)hblo,
                                          (const __half*)hhi, Zl, N, total_tiles);
        edge_fused<<<edge_blocks, 256>>>(Zl, HW, erow, ecol, etype, eval,
                                         outs[l], Ehalf, N);
    }
}

// round 12
// speedup vs baseline: 1.5456x; 1.0428x over previous
#include <cuda_runtime.h>
#include <cuda_fp16.h>
#include <cstdint>

// ---------------------------------------------------------------------------
// CTDExplainer: 3-layer relational GCN explainer. N=8192, D=64, R=3, E=262144.
// Round 12: ngemm_mma re-tiled for occupancy (64 rows/CTA, 128 thr, grid 640,
// 32KB smem) with vectorized W staging (uint2 half stores). Arithmetic
// bit-identical to round 11. zgemm / edge_fused at their measured floors.
// Output layout: [ H (N*64) | z0 (N*N) | z1 | z2 ]  fp32.
// ---------------------------------------------------------------------------

#define MAXN 8192
#define MAXE 262144
#define D 64

__device__ float g_HW  [3 * MAXN * D];
__device__ float g_aggA[MAXN * D];
__device__ float g_aggB[MAXN * D];
__device__ uint2 g_hbhi[MAXN * D / 4];
__device__ uint2 g_hblo[MAXN * D / 4];
__device__ uint2 g_hhi [MAXN * D / 4];

__device__ __forceinline__ uint32_t smem_u32(const void* p) {
    uint32_t a;
    asm("{ .reg .u64 t; cvta.to.shared.u64 t, %1; cvt.u32.u64 %0, t; }" : "=r"(a) : "l"(p));
    return a;
}
__device__ __forceinline__ void ldm_x4(uint32_t& r0, uint32_t& r1, uint32_t& r2,
                                       uint32_t& r3, uint32_t addr) {
    asm volatile("ldmatrix.sync.aligned.m8n8.x4.shared.b16 {%0,%1,%2,%3}, [%4];"
                 : "=r"(r0), "=r"(r1), "=r"(r2), "=r"(r3) : "r"(addr));
}
__device__ __forceinline__ void mma16816(float* c, const uint32_t* a,
                                         uint32_t b0, uint32_t b1) {
    asm volatile(
        "mma.sync.aligned.m16n8k16.row.col.f32.f16.f16.f32 "
        "{%0,%1,%2,%3}, {%4,%5,%6,%7}, {%8,%9}, {%0,%1,%2,%3};"
        : "+f"(c[0]), "+f"(c[1]), "+f"(c[2]), "+f"(c[3])
        : "r"(a[0]), "r"(a[1]), "r"(a[2]), "r"(a[3]), "r"(b0), "r"(b1));
}
__device__ __forceinline__ void cpa16(uint32_t saddr, const void* gaddr) {
    asm volatile("cp.async.cg.shared.global [%0], [%1], 16;"
                 :: "r"(saddr), "l"(gaddr));
}

// ---------------- HMMA per-layer small GEMMs (LN/relu/concat fused) ---------
// grid = (N/64, 5), 128 threads. blockIdx.y selects:
//   0: Hb = base(In) @ bilin -> hbhi/hblo; also exports hhi = fp16(base(In))
//   1..3: HW[y-1] = act(In) @ W_rel[y-1]
//   4: agg = act(In) @ W_root + bias
// base(In) = LN(In) for layers>0 (lng != null), raw for layer 0.
// In rows come from inA, or inB for rows >= nxrows (layer-0 concat).
// 3 fp16 terms: Ihi*Whi + Ilo*Whi + Ihi*Wlo  (error ~2^-22).
#define NG_IHI 0
#define NG_ILO 8192
#define NG_WHI 16384
#define NG_WLO 24576
#define NG_TOT 32768

__global__ void __launch_bounds__(128) ngemm_mma(
    const float* __restrict__ inA, const float* __restrict__ inB, int nxrows,
    const float* __restrict__ lng, const float* __restrict__ lnb,
    const float* __restrict__ bilin, const float* __restrict__ Wrel,
    const float* __restrict__ Wroot, const float* __restrict__ bias,
    __half2* __restrict__ hbhi, __half2* __restrict__ hblo,
    __half2* __restrict__ hhi, float* __restrict__ HW,
    float* __restrict__ agg, int relu, int N) {
    extern __shared__ __align__(16) char smem[];
    const int tid  = threadIdx.x;
    const int row0 = blockIdx.x * 64;
    const int o    = blockIdx.y;
    const uint32_t sb = smem_u32(smem);

    const float* W = (o == 0) ? bilin : (o < 4) ? Wrel + (size_t)(o - 1) * 4096 : Wroot;
    const int act = (o > 0) ? relu : 0;

    // stage W transposed (Wt[n][k]) as fp16 hi/lo, swizzled; 4-k quads, uint2 stores
    for (int q = tid; q < 1024; q += 128) {
        const int k0 = (q >> 6) << 2;         // 0,4,...,60
        const int n  = q & 63;
        __half hs[4], ls[4];
#pragma unroll
        for (int j = 0; j < 4; j++) {
            float w = W[(k0 + j) * 64 + n];
            __half h = __float2half_rn(w);
            hs[j] = h;
            ls[j] = __float2half_rn(w - __half2float(h));
        }
        uint32_t unit = (uint32_t)(k0 >> 3) ^ (uint32_t)(n & 7);
        uint32_t byte = n * 128 + unit * 16 + (k0 & 7) * 2;
        *(uint2*)(smem + NG_WHI + byte) = *(uint2*)hs;
        *(uint2*)(smem + NG_WLO + byte) = *(uint2*)ls;
    }

    // stage 64 input rows: LN / act / exports, fp16 hi/lo swizzled
    {
        const int r    = tid >> 1;            // 0..63
        const int hlf  = tid & 1;
        const int gr   = row0 + r;
        const float* src = (inB && gr >= nxrows)
                         ? (inB + (size_t)(gr - nxrows) * 64 + hlf * 32)
                         : (inA + (size_t)gr * 64 + hlf * 32);
        float v[32];
#pragma unroll
        for (int i = 0; i < 8; i++) {
            float4 t = *(const float4*)(src + i * 4);
            v[i*4+0] = t.x; v[i*4+1] = t.y; v[i*4+2] = t.z; v[i*4+3] = t.w;
        }
        if (lng) {
            float s = 0.f, q = 0.f;
#pragma unroll
            for (int i = 0; i < 32; i++) { s += v[i]; q += v[i] * v[i]; }
            s += __shfl_xor_sync(0xffffffffu, s, 1);
            q += __shfl_xor_sync(0xffffffffu, q, 1);
            float mu  = s * (1.f / 64.f);
            float inv = rsqrtf(q * (1.f / 64.f) - mu * mu + 1e-5f);
#pragma unroll
            for (int i = 0; i < 32; i++) {
                int c = hlf * 32 + i;
                v[i] = (v[i] - mu) * inv * lng[c] + lnb[c];
            }
        }
        if (o == 0) {
            __half2* dst = hhi + ((size_t)gr * 64 + hlf * 32) / 2;
#pragma unroll
            for (int i = 0; i < 16; i++)
                dst[i] = __halves2half2(__float2half_rn(v[2*i]),
                                        __float2half_rn(v[2*i+1]));
        } else if (act) {
#pragma unroll
            for (int i = 0; i < 32; i++) v[i] = fmaxf(v[i], 0.f);
        }
        const int r7 = r & 7;
#pragma unroll
        for (int u = 0; u < 4; u++) {
            __half hs[8], ls[8];
#pragma unroll
            for (int j = 0; j < 8; j++) {
                float x = v[u * 8 + j];
                __half h = __float2half_rn(x);
                hs[j] = h;
                ls[j] = __float2half_rn(x - __half2float(h));
            }
            uint32_t unit = (uint32_t)(hlf * 4 + u) ^ (uint32_t)r7;
            uint32_t byte = r * 128 + unit * 16;
            *(uint4*)(smem + NG_IHI + byte) = *(uint4*)hs;
            *(uint4*)(smem + NG_ILO + byte) = *(uint4*)ls;
        }
    }
    __syncthreads();

    // MMA: warp w handles rows wm..wm+15, full n=64
    const int lane = tid & 31;
    const int wid  = tid >> 5;          // 0..3
    const int wm   = wid * 16;
    const int a_row = wm + (lane & 15);
    const int a_r7  = a_row & 7;
    const int au    = lane >> 4;
    const int b_row = (lane & 7) + (((lane >> 4) & 1) << 3);
    const int b_r7  = b_row & 7;
    const int bu    = (lane >> 3) & 1;

    const uint32_t ahib = sb + NG_IHI + a_row * 128;
    const uint32_t alob = sb + NG_ILO + a_row * 128;
    const uint32_t whib = sb + NG_WHI + b_row * 128;
    const uint32_t wlob = sb + NG_WLO + b_row * 128;

    float acc[8][4];
#pragma unroll
    for (int i = 0; i < 8; i++)
#pragma unroll
        for (int j = 0; j < 4; j++) acc[i][j] = 0.f;

#pragma unroll
    for (int kc = 0; kc < 4; kc++) {
        const uint32_t aoff = ((((kc << 1) + au) ^ a_r7) << 4);
        const uint32_t boff = ((((kc << 1) + bu) ^ b_r7) << 4);
        uint32_t Ah[4], Al[4], bh[16], bl[16];
        ldm_x4(Ah[0], Ah[1], Ah[2], Ah[3], ahib + aoff);
        ldm_x4(Al[0], Al[1], Al[2], Al[3], alob + aoff);
#pragma unroll
        for (int nt = 0; nt < 4; nt++) {
            ldm_x4(bh[4*nt], bh[4*nt+1], bh[4*nt+2], bh[4*nt+3],
                   whib + boff + nt * 16 * 128);
            ldm_x4(bl[4*nt], bl[4*nt+1], bl[4*nt+2], bl[4*nt+3],
                   wlob + boff + nt * 16 * 128);
        }
#pragma unroll
        for (int ni = 0; ni < 8; ni++) {
            const int bi = (ni >> 1) * 4 + (ni & 1) * 2;
            mma16816(acc[ni], Ah, bh[bi], bh[bi + 1]);
        }
#pragma unroll
        for (int ni = 0; ni < 8; ni++) {
            const int bi = (ni >> 1) * 4 + (ni & 1) * 2;
            mma16816(acc[ni], Al, bh[bi], bh[bi + 1]);
        }
#pragma unroll
        for (int ni = 0; ni < 8; ni++) {
            const int bi = (ni >> 1) * 4 + (ni & 1) * 2;
            mma16816(acc[ni], Ah, bl[bi], bl[bi + 1]);
        }
    }

    // epilogue
    const int er = lane >> 2;
    const int ec = (lane & 3) * 2;
    const int gr = row0 + wm + er;
    if (o == 0) {
#pragma unroll
        for (int ni = 0; ni < 8; ni++) {
            float* f = acc[ni];
            int col = ni * 8 + ec;
            size_t i0 = ((size_t)gr * 64 + col) / 2;
            size_t i1 = ((size_t)(gr + 8) * 64 + col) / 2;
            __half h0 = __float2half_rn(f[0]), h1 = __float2half_rn(f[1]);
            __half h2 = __float2half_rn(f[2]), h3 = __float2half_rn(f[3]);
            hbhi[i0] = __halves2half2(h0, h1);
            hbhi[i1] = __halves2half2(h2, h3);
            hblo[i0] = __halves2half2(__float2half_rn(f[0] - __half2float(h0)),
                                      __float2half_rn(f[1] - __half2float(h1)));
            hblo[i1] = __halves2half2(__float2half_rn(f[2] - __half2float(h2)),
                                      __float2half_rn(f[3] - __half2float(h3)));
        }
    } else if (o < 4) {
        float* Out = HW + (size_t)(o - 1) * N * 64;
#pragma unroll
        for (int ni = 0; ni < 8; ni++) {
            float* f = acc[ni];
            int col = ni * 8 + ec;
            *(float2*)(Out + (size_t)gr * 64 + col)       = make_float2(f[0], f[1]);
            *(float2*)(Out + (size_t)(gr + 8) * 64 + col) = make_float2(f[2], f[3]);
        }
    } else {
#pragma unroll
        for (int ni = 0; ni < 8; ni++) {
            float* f = acc[ni];
            int col = ni * 8 + ec;
            float b0 = bias[col], b1 = bias[col + 1];
            *(float2*)(agg + (size_t)gr * 64 + col)       = make_float2(f[0] + b0, f[1] + b1);
            *(float2*)(agg + (size_t)(gr + 8) * 64 + col) = make_float2(f[2] + b0, f[3] + b1);
        }
    }
}

// ---------------- persistent HMMA GEMM: C = (Ahi + Alo) @ Bhi^T -------------
// Band-major tile order; A loaded once per band, B double-buffered cp.async.
#define TILEB 16384
#define SM_TOT (4 * TILEB)

__global__ void __launch_bounds__(256, 2) zgemm_mma(
    const __half* __restrict__ Ahi, const __half* __restrict__ Alo,
    const __half* __restrict__ Bhi, float* __restrict__ C, int N,
    int total_tiles) {
    extern __shared__ __align__(16) char smem[];
    const int tid = threadIdx.x;
    const uint32_t sb = smem_u32(smem);

    const int lrow = tid >> 1;
    const int lcu  = (tid & 1) * 4;
    const int lr7  = lrow & 7;
    const int lcol = (tid & 1) * 32;
    uint32_t soff[4];
#pragma unroll
    for (int i = 0; i < 4; i++)
        soff[i] = lrow * 128 + (((lcu + i) ^ lr7) << 4);

    auto loadA = [&](int band) {
        const __half* gA0 = Ahi + (size_t)(band * 128 + lrow) * 64 + lcol;
        const __half* gA1 = Alo + (size_t)(band * 128 + lrow) * 64 + lcol;
#pragma unroll
        for (int i = 0; i < 4; i++) {
            cpa16(sb + 0 * TILEB + soff[i], gA0 + i * 8);
            cpa16(sb + 1 * TILEB + soff[i], gA1 + i * 8);
        }
    };
    auto issueB = [&](int buf, int n0) {
        const __half* gB = Bhi + (size_t)(n0 * 128 + lrow) * 64 + lcol;
        const uint32_t s0 = sb + 2 * TILEB + buf * TILEB;
#pragma unroll
        for (int i = 0; i < 4; i++)
            cpa16(s0 + soff[i], gB + i * 8);
    };

    const int lane = tid & 31;
    const int wid  = tid >> 5;
    const int wm   = (wid & 3) * 32;
    const int wn   = (wid >> 2) * 64;

    const int a_row = wm + (lane & 15);
    const int a_r7  = a_row & 7;
    const int au    = lane >> 4;
    const int b_row = wn + (lane & 7) + (((lane >> 4) & 1) << 3);
    const int b_r7  = b_row & 7;
    const int bu    = (lane >> 3) & 1;
    const int er = lane >> 2;
    const int ec = (lane & 3) * 2;

    uint32_t aoffk[4], boffk[4];
#pragma unroll
    for (int kc = 0; kc < 4; kc++) {
        aoffk[kc] = ((((kc << 1) + au) ^ a_r7) << 4);
        boffk[kc] = ((((kc << 1) + bu) ^ b_r7) << 4);
    }
    const uint32_t abase_row = sb + a_row * 128;
    const uint32_t bbase0    = sb + 2 * TILEB + b_row * 128;

    const int G = gridDim.x;
    const int p = blockIdx.x;
    const int start = (int)(((long long)p * total_tiles) / G);
    const int end   = (int)(((long long)(p + 1) * total_tiles) / G);
    if (start >= end) return;

    int curBand = start >> 6;
    loadA(curBand);
    issueB(0, start & 63);
    asm volatile("cp.async.commit_group;");

    int idx = 0;
    for (int t = start; t < end; t++, idx++) {
        const int band = t >> 6;
        if (band != curBand) {
            loadA(band);
            asm volatile("cp.async.commit_group;");
            curBand = band;
        }
        const int buf = idx & 1;
        if (t + 1 < end) issueB(1 - buf, (t + 1) & 63);
        asm volatile("cp.async.commit_group;");
        asm volatile("cp.async.wait_group 1;");
        __syncthreads();

        const uint32_t bbase_row = bbase0 + (buf ? (uint32_t)TILEB : 0u);

        float acc[16][4];
#pragma unroll
        for (int i = 0; i < 16; i++)
#pragma unroll
            for (int j = 0; j < 4; j++) acc[i][j] = 0.f;

#pragma unroll
        for (int kc = 0; kc < 4; kc++) {
            uint32_t Ah[8], Al[8], bh[16];
            ldm_x4(Ah[0], Ah[1], Ah[2], Ah[3], abase_row + aoffk[kc]);
            ldm_x4(Ah[4], Ah[5], Ah[6], Ah[7], abase_row + aoffk[kc] + 16 * 128);
            ldm_x4(Al[0], Al[1], Al[2], Al[3], abase_row + TILEB + aoffk[kc]);
            ldm_x4(Al[4], Al[5], Al[6], Al[7], abase_row + TILEB + aoffk[kc] + 16 * 128);
#pragma unroll
            for (int nt2 = 0; nt2 < 4; nt2++)
                ldm_x4(bh[4 * nt2], bh[4 * nt2 + 1], bh[4 * nt2 + 2], bh[4 * nt2 + 3],
                       bbase_row + boffk[kc] + nt2 * 16 * 128);
#pragma unroll
            for (int nt2 = 0; nt2 < 4; nt2++) {
                mma16816(acc[2 * nt2],         Ah,     bh[4 * nt2],     bh[4 * nt2 + 1]);
                mma16816(acc[2 * nt2 + 1],     Ah,     bh[4 * nt2 + 2], bh[4 * nt2 + 3]);
                mma16816(acc[8 + 2 * nt2],     Ah + 4, bh[4 * nt2],     bh[4 * nt2 + 1]);
                mma16816(acc[8 + 2 * nt2 + 1], Ah + 4, bh[4 * nt2 + 2], bh[4 * nt2 + 3]);
            }
#pragma unroll
            for (int nt2 = 0; nt2 < 4; nt2++) {
                mma16816(acc[2 * nt2],         Al,     bh[4 * nt2],     bh[4 * nt2 + 1]);
                mma16816(acc[2 * nt2 + 1],     Al,     bh[4 * nt2 + 2], bh[4 * nt2 + 3]);
                mma16816(acc[8 + 2 * nt2],     Al + 4, bh[4 * nt2],     bh[4 * nt2 + 1]);
                mma16816(acc[8 + 2 * nt2 + 1], Al + 4, bh[4 * nt2 + 2], bh[4 * nt2 + 3]);
            }
        }

        const int m0 = band * 128;
        const int n0 = (t & 63) * 128;
#pragma unroll
        for (int mi = 0; mi < 2; mi++)
#pragma unroll
            for (int ni = 0; ni < 8; ni++) {
                float* f = acc[mi * 8 + ni];
                size_t r = (size_t)(m0 + wm + mi * 16 + er);
                int col = n0 + wn + ni * 8 + ec;
                *(float2*)(C + r * N + col)       = make_float2(f[0], f[1]);
                *(float2*)(C + (r + 8) * N + col) = make_float2(f[2], f[3]);
            }
        __syncthreads();
    }
}

// ---------------- fused edge gather + scatter: 2 edges / 16-lane group ------
__global__ void edge_fused(const float* __restrict__ Z, const float* __restrict__ HW,
                           const int* __restrict__ row, const int* __restrict__ col,
                           const int* __restrict__ et, const float* __restrict__ ev,
                           float* __restrict__ agg, int Ehalf, int N) {
    int gi  = blockIdx.x * blockDim.x + threadIdx.x;
    int e0  = gi >> 4;
    int sub = threadIdx.x & 15;
    if (e0 >= Ehalf) return;
    int e1 = e0 + Ehalf;

    int r0 = row[e0], c0 = col[e0], t0 = et[e0];
    int r1 = row[e1], c1 = col[e1], t1 = et[e1];
    float z0 = Z[(size_t)r0 * N + c0];
    float z1 = Z[(size_t)r1 * N + c1];
    float av0 = z0 * ev[e0];
    float av1 = z1 * ev[e1];
    float4 m0 = ((const float4*)(HW + ((size_t)t0 * N + c0) * 64))[sub];
    float4 m1 = ((const float4*)(HW + ((size_t)t1 * N + c1) * 64))[sub];

    float* d0 = agg + (size_t)r0 * 64 + sub * 4;
    float* d1 = agg + (size_t)r1 * 64 + sub * 4;
    asm volatile("red.global.add.v4.f32 [%0], {%1, %2, %3, %4};"
                 :: "l"(d0), "f"(m0.x * av0), "f"(m0.y * av0),
                    "f"(m0.z * av0), "f"(m0.w * av0) : "memory");
    asm volatile("red.global.add.v4.f32 [%0], {%1, %2, %3, %4};"
                 :: "l"(d1), "f"(m1.x * av1), "f"(m1.y * av1),
                    "f"(m1.z * av1), "f"(m1.w * av1) : "memory");
}

// ---------------------------------------------------------------------------
extern "C" void kernel_launch(void* const* d_in, const int* in_sizes, int n_in,
                              void* d_out, int out_size) {
    const float* x       = (const float*)d_in[0];
    const float* emb     = (const float*)d_in[1];
    const float* bilin   = (const float*)d_in[2];
    const float* eval    = (const float*)d_in[3];
    const float* W_root  = (const float*)d_in[4];
    const float* W_rel   = (const float*)d_in[5];
    const float* bias    = (const float*)d_in[6];
    const float* ln_g    = (const float*)d_in[7];
    const float* ln_b    = (const float*)d_in[8];
    const int*   erow    = (const int*)d_in[9];
    const int*   ecol    = (const int*)d_in[10];
    const int*   etype   = (const int*)d_in[11];

    const int NX = in_sizes[0] / D;
    const int NE = in_sizes[1] / D;
    const int N  = NX + NE;
    const int E  = in_sizes[3];

    float* out   = (float*)d_out;
    float* Hout  = out;
    float* Zbase = out + (size_t)N * D;

    float *HW, *aggA, *aggB;
    uint2 *hbhi, *hblo, *hhi;
    cudaGetSymbolAddress((void**)&HW,   g_HW);
    cudaGetSymbolAddress((void**)&aggA, g_aggA);
    cudaGetSymbolAddress((void**)&aggB, g_aggB);
    cudaGetSymbolAddress((void**)&hbhi, g_hbhi);
    cudaGetSymbolAddress((void**)&hblo, g_hblo);
    cudaGetSymbolAddress((void**)&hhi,  g_hhi);

    cudaFuncSetAttribute(zgemm_mma, cudaFuncAttributeMaxDynamicSharedMemorySize, SM_TOT);
    cudaFuncSetAttribute(ngemm_mma, cudaFuncAttributeMaxDynamicSharedMemorySize, NG_TOT);

    int nsm = 148;
    cudaDeviceGetAttribute(&nsm, cudaDevAttrMultiProcessorCount, 0);

    const int tiles_n = N / 128;
    const int total_tiles = tiles_n * tiles_n;
    const int zgrid = 2 * nsm;
    dim3 ngrid(N / 64, 5);
    const int Ehalf = E / 2;
    const int edge_blocks = (Ehalf * 16 + 255) / 256;

    const float* insA[3] = { x, aggA, aggB };
    const float* insB[3] = { emb, nullptr, nullptr };
    float*       outs[3] = { aggA, aggB, Hout };

    for (int l = 0; l < 3; l++) {
        float* Zl   = Zbase + (size_t)l * N * N;
        const float* lng = (l == 0) ? nullptr : ln_g + (size_t)(l - 1) * D;
        const float* lnb = (l == 0) ? nullptr : ln_b + (size_t)(l - 1) * D;
        int relu = (l > 0) ? 1 : 0;

        ngemm_mma<<<ngrid, 128, NG_TOT>>>(insA[l], insB[l], NX, lng, lnb,
                                          bilin + (size_t)l * D * D,
                                          W_rel + (size_t)l * 3 * D * D,
                                          W_root + (size_t)l * D * D,
                                          bias + (size_t)l * D,
                                          (__half2*)hbhi, (__half2*)hblo,
                                          (__half2*)hhi, HW, outs[l], relu, N);
        zgemm_mma<<<zgrid, 256, SM_TOT>>>((const __half*)hbhi, (const __half*)hblo,
                                          (const __half*)hhi, Zl, N, total_tiles);
        edge_fused<<<edge_blocks, 256>>>(Zl, HW, erow, ecol, etype, eval,
                                         outs[l], Ehalf, N);
    }
}

// round 13
// speedup vs baseline: 1.5510x; 1.0035x over previous
#include <cuda_runtime.h>
#include <cuda_fp16.h>
#include <cstdint>

// ---------------------------------------------------------------------------
// CTDExplainer: 3-layer relational GCN explainer. N=8192, D=64, R=3, E=262144.
// Round 13: ngemm_mma de-spilled — __launch_bounds__(128,4) raises the reg cap
// from the 56 ptxas chose (live set ~90 was spilling B fragments to local,
// seen as L1 40% / tensor 8.5%), and the inner loop is restructured per
// nt-pair to shrink peak live registers (~64). Per-accumulator MMA order is
// unchanged -> bit-identical numerics. zgemm / edge_fused at measured floors.
// Output layout: [ H (N*64) | z0 (N*N) | z1 | z2 ]  fp32.
// ---------------------------------------------------------------------------

#define MAXN 8192
#define MAXE 262144
#define D 64

__device__ float g_HW  [3 * MAXN * D];
__device__ float g_aggA[MAXN * D];
__device__ float g_aggB[MAXN * D];
__device__ uint2 g_hbhi[MAXN * D / 4];
__device__ uint2 g_hblo[MAXN * D / 4];
__device__ uint2 g_hhi [MAXN * D / 4];

__device__ __forceinline__ uint32_t smem_u32(const void* p) {
    uint32_t a;
    asm("{ .reg .u64 t; cvta.to.shared.u64 t, %1; cvt.u32.u64 %0, t; }" : "=r"(a) : "l"(p));
    return a;
}
__device__ __forceinline__ void ldm_x4(uint32_t& r0, uint32_t& r1, uint32_t& r2,
                                       uint32_t& r3, uint32_t addr) {
    asm volatile("ldmatrix.sync.aligned.m8n8.x4.shared.b16 {%0,%1,%2,%3}, [%4];"
                 : "=r"(r0), "=r"(r1), "=r"(r2), "=r"(r3) : "r"(addr));
}
__device__ __forceinline__ void mma16816(float* c, const uint32_t* a,
                                         uint32_t b0, uint32_t b1) {
    asm volatile(
        "mma.sync.aligned.m16n8k16.row.col.f32.f16.f16.f32 "
        "{%0,%1,%2,%3}, {%4,%5,%6,%7}, {%8,%9}, {%0,%1,%2,%3};"
        : "+f"(c[0]), "+f"(c[1]), "+f"(c[2]), "+f"(c[3])
        : "r"(a[0]), "r"(a[1]), "r"(a[2]), "r"(a[3]), "r"(b0), "r"(b1));
}
__device__ __forceinline__ void cpa16(uint32_t saddr, const void* gaddr) {
    asm volatile("cp.async.cg.shared.global [%0], [%1], 16;"
                 :: "r"(saddr), "l"(gaddr));
}

// ---------------- HMMA per-layer small GEMMs (LN/relu/concat fused) ---------
// grid = (N/64, 5), 128 threads. blockIdx.y selects:
//   0: Hb = base(In) @ bilin -> hbhi/hblo; also exports hhi = fp16(base(In))
//   1..3: HW[y-1] = act(In) @ W_rel[y-1]
//   4: agg = act(In) @ W_root + bias
// 3 fp16 terms: Ihi*Whi + Ilo*Whi + Ihi*Wlo  (error ~2^-22).
#define NG_IHI 0
#define NG_ILO 8192
#define NG_WHI 16384
#define NG_WLO 24576
#define NG_TOT 32768

__global__ void __launch_bounds__(128, 4) ngemm_mma(
    const float* __restrict__ inA, const float* __restrict__ inB, int nxrows,
    const float* __restrict__ lng, const float* __restrict__ lnb,
    const float* __restrict__ bilin, const float* __restrict__ Wrel,
    const float* __restrict__ Wroot, const float* __restrict__ bias,
    __half2* __restrict__ hbhi, __half2* __restrict__ hblo,
    __half2* __restrict__ hhi, float* __restrict__ HW,
    float* __restrict__ agg, int relu, int N) {
    extern __shared__ __align__(16) char smem[];
    const int tid  = threadIdx.x;
    const int row0 = blockIdx.x * 64;
    const int o    = blockIdx.y;
    const uint32_t sb = smem_u32(smem);

    const float* W = (o == 0) ? bilin : (o < 4) ? Wrel + (size_t)(o - 1) * 4096 : Wroot;
    const int act = (o > 0) ? relu : 0;

    // stage W transposed (Wt[n][k]) as fp16 hi/lo, swizzled; 4-k quads
    for (int q = tid; q < 1024; q += 128) {
        const int k0 = (q >> 6) << 2;
        const int n  = q & 63;
        __half hs[4], ls[4];
#pragma unroll
        for (int j = 0; j < 4; j++) {
            float w = W[(k0 + j) * 64 + n];
            __half h = __float2half_rn(w);
            hs[j] = h;
            ls[j] = __float2half_rn(w - __half2float(h));
        }
        uint32_t unit = (uint32_t)(k0 >> 3) ^ (uint32_t)(n & 7);
        uint32_t byte = n * 128 + unit * 16 + (k0 & 7) * 2;
        *(uint2*)(smem + NG_WHI + byte) = *(uint2*)hs;
        *(uint2*)(smem + NG_WLO + byte) = *(uint2*)ls;
    }

    // stage 64 input rows: LN / act / exports, fp16 hi/lo swizzled
    {
        const int r    = tid >> 1;
        const int hlf  = tid & 1;
        const int gr   = row0 + r;
        const float* src = (inB && gr >= nxrows)
                         ? (inB + (size_t)(gr - nxrows) * 64 + hlf * 32)
                         : (inA + (size_t)gr * 64 + hlf * 32);
        float v[32];
#pragma unroll
        for (int i = 0; i < 8; i++) {
            float4 t = *(const float4*)(src + i * 4);
            v[i*4+0] = t.x; v[i*4+1] = t.y; v[i*4+2] = t.z; v[i*4+3] = t.w;
        }
        if (lng) {
            float s = 0.f, q = 0.f;
#pragma unroll
            for (int i = 0; i < 32; i++) { s += v[i]; q += v[i] * v[i]; }
            s += __shfl_xor_sync(0xffffffffu, s, 1);
            q += __shfl_xor_sync(0xffffffffu, q, 1);
            float mu  = s * (1.f / 64.f);
            float inv = rsqrtf(q * (1.f / 64.f) - mu * mu + 1e-5f);
#pragma unroll
            for (int i = 0; i < 32; i++) {
                int c = hlf * 32 + i;
                v[i] = (v[i] - mu) * inv * lng[c] + lnb[c];
            }
        }
        if (o == 0) {
            __half2* dst = hhi + ((size_t)gr * 64 + hlf * 32) / 2;
#pragma unroll
            for (int i = 0; i < 16; i++)
                dst[i] = __halves2half2(__float2half_rn(v[2*i]),
                                        __float2half_rn(v[2*i+1]));
        } else if (act) {
#pragma unroll
            for (int i = 0; i < 32; i++) v[i] = fmaxf(v[i], 0.f);
        }
        const int r7 = r & 7;
#pragma unroll
        for (int u = 0; u < 4; u++) {
            __half hs[8], ls[8];
#pragma unroll
            for (int j = 0; j < 8; j++) {
                float x = v[u * 8 + j];
                __half h = __float2half_rn(x);
                hs[j] = h;
                ls[j] = __float2half_rn(x - __half2float(h));
            }
            uint32_t unit = (uint32_t)(hlf * 4 + u) ^ (uint32_t)r7;
            uint32_t byte = r * 128 + unit * 16;
            *(uint4*)(smem + NG_IHI + byte) = *(uint4*)hs;
            *(uint4*)(smem + NG_ILO + byte) = *(uint4*)ls;
        }
    }
    __syncthreads();

    // MMA: warp w handles rows wm..wm+15, full n=64
    const int lane = tid & 31;
    const int wid  = tid >> 5;
    const int wm   = wid * 16;
    const int a_row = wm + (lane & 15);
    const int a_r7  = a_row & 7;
    const int au    = lane >> 4;
    const int b_row = (lane & 7) + (((lane >> 4) & 1) << 3);
    const int b_r7  = b_row & 7;
    const int bu    = (lane >> 3) & 1;

    const uint32_t ahib = sb + NG_IHI + a_row * 128;
    const uint32_t alob = sb + NG_ILO + a_row * 128;
    const uint32_t whib = sb + NG_WHI + b_row * 128;
    const uint32_t wlob = sb + NG_WLO + b_row * 128;

    float acc[8][4];
#pragma unroll
    for (int i = 0; i < 8; i++)
#pragma unroll
        for (int j = 0; j < 4; j++) acc[i][j] = 0.f;

#pragma unroll
    for (int kc = 0; kc < 4; kc++) {
        const uint32_t aoff = ((((kc << 1) + au) ^ a_r7) << 4);
        const uint32_t boff = ((((kc << 1) + bu) ^ b_r7) << 4);
        uint32_t Ah[4], Al[4];
        ldm_x4(Ah[0], Ah[1], Ah[2], Ah[3], ahib + aoff);
        ldm_x4(Al[0], Al[1], Al[2], Al[3], alob + aoff);
        // per-nt processing: peak live = Ah(4)+Al(4)+bh(4)+bl(4)+acc(32)
        // per-accumulator order: Ah*bh, Al*bh, Ah*bl (identical to r11/r12)
#pragma unroll
        for (int nt = 0; nt < 4; nt++) {
            uint32_t bh[4], bl[4];
            ldm_x4(bh[0], bh[1], bh[2], bh[3], whib + boff + nt * 16 * 128);
            ldm_x4(bl[0], bl[1], bl[2], bl[3], wlob + boff + nt * 16 * 128);
            float* a0 = acc[2 * nt];
            float* a1 = acc[2 * nt + 1];
            mma16816(a0, Ah, bh[0], bh[1]);
            mma16816(a1, Ah, bh[2], bh[3]);
            mma16816(a0, Al, bh[0], bh[1]);
            mma16816(a1, Al, bh[2], bh[3]);
            mma16816(a0, Ah, bl[0], bl[1]);
            mma16816(a1, Ah, bl[2], bl[3]);
        }
    }

    // epilogue
    const int er = lane >> 2;
    const int ec = (lane & 3) * 2;
    const int gr = row0 + wm + er;
    if (o == 0) {
#pragma unroll
        for (int ni = 0; ni < 8; ni++) {
            float* f = acc[ni];
            int col = ni * 8 + ec;
            size_t i0 = ((size_t)gr * 64 + col) / 2;
            size_t i1 = ((size_t)(gr + 8) * 64 + col) / 2;
            __half h0 = __float2half_rn(f[0]), h1 = __float2half_rn(f[1]);
            __half h2 = __float2half_rn(f[2]), h3 = __float2half_rn(f[3]);
            hbhi[i0] = __halves2half2(h0, h1);
            hbhi[i1] = __halves2half2(h2, h3);
            hblo[i0] = __halves2half2(__float2half_rn(f[0] - __half2float(h0)),
                                      __float2half_rn(f[1] - __half2float(h1)));
            hblo[i1] = __halves2half2(__float2half_rn(f[2] - __half2float(h2)),
                                      __float2half_rn(f[3] - __half2float(h3)));
        }
    } else if (o < 4) {
        float* Out = HW + (size_t)(o - 1) * N * 64;
#pragma unroll
        for (int ni = 0; ni < 8; ni++) {
            float* f = acc[ni];
            int col = ni * 8 + ec;
            *(float2*)(Out + (size_t)gr * 64 + col)       = make_float2(f[0], f[1]);
            *(float2*)(Out + (size_t)(gr + 8) * 64 + col) = make_float2(f[2], f[3]);
        }
    } else {
#pragma unroll
        for (int ni = 0; ni < 8; ni++) {
            float* f = acc[ni];
            int col = ni * 8 + ec;
            float b0 = bias[col], b1 = bias[col + 1];
            *(float2*)(agg + (size_t)gr * 64 + col)       = make_float2(f[0] + b0, f[1] + b1);
            *(float2*)(agg + (size_t)(gr + 8) * 64 + col) = make_float2(f[2] + b0, f[3] + b1);
        }
    }
}

// ---------------- persistent HMMA GEMM: C = (Ahi + Alo) @ Bhi^T -------------
// Band-major tile order; A loaded once per band, B double-buffered cp.async.
#define TILEB 16384
#define SM_TOT (4 * TILEB)

__global__ void __launch_bounds__(256, 2) zgemm_mma(
    const __half* __restrict__ Ahi, const __half* __restrict__ Alo,
    const __half* __restrict__ Bhi, float* __restrict__ C, int N,
    int total_tiles) {
    extern __shared__ __align__(16) char smem[];
    const int tid = threadIdx.x;
    const uint32_t sb = smem_u32(smem);

    const int lrow = tid >> 1;
    const int lcu  = (tid & 1) * 4;
    const int lr7  = lrow & 7;
    const int lcol = (tid & 1) * 32;
    uint32_t soff[4];
#pragma unroll
    for (int i = 0; i < 4; i++)
        soff[i] = lrow * 128 + (((lcu + i) ^ lr7) << 4);

    auto loadA = [&](int band) {
        const __half* gA0 = Ahi + (size_t)(band * 128 + lrow) * 64 + lcol;
        const __half* gA1 = Alo + (size_t)(band * 128 + lrow) * 64 + lcol;
#pragma unroll
        for (int i = 0; i < 4; i++) {
            cpa16(sb + 0 * TILEB + soff[i], gA0 + i * 8);
            cpa16(sb + 1 * TILEB + soff[i], gA1 + i * 8);
        }
    };
    auto issueB = [&](int buf, int n0) {
        const __half* gB = Bhi + (size_t)(n0 * 128 + lrow) * 64 + lcol;
        const uint32_t s0 = sb + 2 * TILEB + buf * TILEB;
#pragma unroll
        for (int i = 0; i < 4; i++)
            cpa16(s0 + soff[i], gB + i * 8);
    };

    const int lane = tid & 31;
    const int wid  = tid >> 5;
    const int wm   = (wid & 3) * 32;
    const int wn   = (wid >> 2) * 64;

    const int a_row = wm + (lane & 15);
    const int a_r7  = a_row & 7;
    const int au    = lane >> 4;
    const int b_row = wn + (lane & 7) + (((lane >> 4) & 1) << 3);
    const int b_r7  = b_row & 7;
    const int bu    = (lane >> 3) & 1;
    const int er = lane >> 2;
    const int ec = (lane & 3) * 2;

    uint32_t aoffk[4], boffk[4];
#pragma unroll
    for (int kc = 0; kc < 4; kc++) {
        aoffk[kc] = ((((kc << 1) + au) ^ a_r7) << 4);
        boffk[kc] = ((((kc << 1) + bu) ^ b_r7) << 4);
    }
    const uint32_t abase_row = sb + a_row * 128;
    const uint32_t bbase0    = sb + 2 * TILEB + b_row * 128;

    const int G = gridDim.x;
    const int p = blockIdx.x;
    const int start = (int)(((long long)p * total_tiles) / G);
    const int end   = (int)(((long long)(p + 1) * total_tiles) / G);
    if (start >= end) return;

    int curBand = start >> 6;
    loadA(curBand);
    issueB(0, start & 63);
    asm volatile("cp.async.commit_group;");

    int idx = 0;
    for (int t = start; t < end; t++, idx++) {
        const int band = t >> 6;
        if (band != curBand) {
            loadA(band);
            asm volatile("cp.async.commit_group;");
            curBand = band;
        }
        const int buf = idx & 1;
        if (t + 1 < end) issueB(1 - buf, (t + 1) & 63);
        asm volatile("cp.async.commit_group;");
        asm volatile("cp.async.wait_group 1;");
        __syncthreads();

        const uint32_t bbase_row = bbase0 + (buf ? (uint32_t)TILEB : 0u);

        float acc[16][4];
#pragma unroll
        for (int i = 0; i < 16; i++)
#pragma unroll
            for (int j = 0; j < 4; j++) acc[i][j] = 0.f;

#pragma unroll
        for (int kc = 0; kc < 4; kc++) {
            uint32_t Ah[8], Al[8], bh[16];
            ldm_x4(Ah[0], Ah[1], Ah[2], Ah[3], abase_row + aoffk[kc]);
            ldm_x4(Ah[4], Ah[5], Ah[6], Ah[7], abase_row + aoffk[kc] + 16 * 128);
            ldm_x4(Al[0], Al[1], Al[2], Al[3], abase_row + TILEB + aoffk[kc]);
            ldm_x4(Al[4], Al[5], Al[6], Al[7], abase_row + TILEB + aoffk[kc] + 16 * 128);
#pragma unroll
            for (int nt2 = 0; nt2 < 4; nt2++)
                ldm_x4(bh[4 * nt2], bh[4 * nt2 + 1], bh[4 * nt2 + 2], bh[4 * nt2 + 3],
                       bbase_row + boffk[kc] + nt2 * 16 * 128);
#pragma unroll
            for (int nt2 = 0; nt2 < 4; nt2++) {
                mma16816(acc[2 * nt2],         Ah,     bh[4 * nt2],     bh[4 * nt2 + 1]);
                mma16816(acc[2 * nt2 + 1],     Ah,     bh[4 * nt2 + 2], bh[4 * nt2 + 3]);
                mma16816(acc[8 + 2 * nt2],     Ah + 4, bh[4 * nt2],     bh[4 * nt2 + 1]);
                mma16816(acc[8 + 2 * nt2 + 1], Ah + 4, bh[4 * nt2 + 2], bh[4 * nt2 + 3]);
            }
#pragma unroll
            for (int nt2 = 0; nt2 < 4; nt2++) {
                mma16816(acc[2 * nt2],         Al,     bh[4 * nt2],     bh[4 * nt2 + 1]);
                mma16816(acc[2 * nt2 + 1],     Al,     bh[4 * nt2 + 2], bh[4 * nt2 + 3]);
                mma16816(acc[8 + 2 * nt2],     Al + 4, bh[4 * nt2],     bh[4 * nt2 + 1]);
                mma16816(acc[8 + 2 * nt2 + 1], Al + 4, bh[4 * nt2 + 2], bh[4 * nt2 + 3]);
            }
        }

        const int m0 = band * 128;
        const int n0 = (t & 63) * 128;
#pragma unroll
        for (int mi = 0; mi < 2; mi++)
#pragma unroll
            for (int ni = 0; ni < 8; ni++) {
                float* f = acc[mi * 8 + ni];
                size_t r = (size_t)(m0 + wm + mi * 16 + er);
                int col = n0 + wn + ni * 8 + ec;
                *(float2*)(C + r * N + col)       = make_float2(f[0], f[1]);
                *(float2*)(C + (r + 8) * N + col) = make_float2(f[2], f[3]);
            }
        __syncthreads();
    }
}

// ---------------- fused edge gather + scatter: 2 edges / 16-lane group ------
__global__ void edge_fused(const float* __restrict__ Z, const float* __restrict__ HW,
                           const int* __restrict__ row, const int* __restrict__ col,
                           const int* __restrict__ et, const float* __restrict__ ev,
                           float* __restrict__ agg, int Ehalf, int N) {
    int gi  = blockIdx.x * blockDim.x + threadIdx.x;
    int e0  = gi >> 4;
    int sub = threadIdx.x & 15;
    if (e0 >= Ehalf) return;
    int e1 = e0 + Ehalf;

    int r0 = row[e0], c0 = col[e0], t0 = et[e0];
    int r1 = row[e1], c1 = col[e1], t1 = et[e1];
    float z0 = Z[(size_t)r0 * N + c0];
    float z1 = Z[(size_t)r1 * N + c1];
    float av0 = z0 * ev[e0];
    float av1 = z1 * ev[e1];
    float4 m0 = ((const float4*)(HW + ((size_t)t0 * N + c0) * 64))[sub];
    float4 m1 = ((const float4*)(HW + ((size_t)t1 * N + c1) * 64))[sub];

    float* d0 = agg + (size_t)r0 * 64 + sub * 4;
    float* d1 = agg + (size_t)r1 * 64 + sub * 4;
    asm volatile("red.global.add.v4.f32 [%0], {%1, %2, %3, %4};"
                 :: "l"(d0), "f"(m0.x * av0), "f"(m0.y * av0),
                    "f"(m0.z * av0), "f"(m0.w * av0) : "memory");
    asm volatile("red.global.add.v4.f32 [%0], {%1, %2, %3, %4};"
                 :: "l"(d1), "f"(m1.x * av1), "f"(m1.y * av1),
                    "f"(m1.z * av1), "f"(m1.w * av1) : "memory");
}

// ---------------------------------------------------------------------------
extern "C" void kernel_launch(void* const* d_in, const int* in_sizes, int n_in,
                              void* d_out, int out_size) {
    const float* x       = (const float*)d_in[0];
    const float* emb     = (const float*)d_in[1];
    const float* bilin   = (const float*)d_in[2];
    const float* eval    = (const float*)d_in[3];
    const float* W_root  = (const float*)d_in[4];
    const float* W_rel   = (const float*)d_in[5];
    const float* bias    = (const float*)d_in[6];
    const float* ln_g    = (const float*)d_in[7];
    const float* ln_b    = (const float*)d_in[8];
    const int*   erow    = (const int*)d_in[9];
    const int*   ecol    = (const int*)d_in[10];
    const int*   etype   = (const int*)d_in[11];

    const int NX = in_sizes[0] / D;
    const int NE = in_sizes[1] / D;
    const int N  = NX + NE;
    const int E  = in_sizes[3];

    float* out   = (float*)d_out;
    float* Hout  = out;
    float* Zbase = out + (size_t)N * D;

    float *HW, *aggA, *aggB;
    uint2 *hbhi, *hblo, *hhi;
    cudaGetSymbolAddress((void**)&HW,   g_HW);
    cudaGetSymbolAddress((void**)&aggA, g_aggA);
    cudaGetSymbolAddress((void**)&aggB, g_aggB);
    cudaGetSymbolAddress((void**)&hbhi, g_hbhi);
    cudaGetSymbolAddress((void**)&hblo, g_hblo);
    cudaGetSymbolAddress((void**)&hhi,  g_hhi);

    cudaFuncSetAttribute(zgemm_mma, cudaFuncAttributeMaxDynamicSharedMemorySize, SM_TOT);
    cudaFuncSetAttribute(ngemm_mma, cudaFuncAttributeMaxDynamicSharedMemorySize, NG_TOT);

    int nsm = 148;
    cudaDeviceGetAttribute(&nsm, cudaDevAttrMultiProcessorCount, 0);

    const int tiles_n = N / 128;
    const int total_tiles = tiles_n * tiles_n;
    const int zgrid = 2 * nsm;
    dim3 ngrid(N / 64, 5);
    const int Ehalf = E / 2;
    const int edge_blocks = (Ehalf * 16 + 255) / 256;

    const float* insA[3] = { x, aggA, aggB };
    const float* insB[3] = { emb, nullptr, nullptr };
    float*       outs[3] = { aggA, aggB, Hout };

    for (int l = 0; l < 3; l++) {
        float* Zl   = Zbase + (size_t)l * N * N;
        const float* lng = (l == 0) ? nullptr : ln_g + (size_t)(l - 1) * D;
        const float* lnb = (l == 0) ? nullptr : ln_b + (size_t)(l - 1) * D;
        int relu = (l > 0) ? 1 : 0;

        ngemm_mma<<<ngrid, 128, NG_TOT>>>(insA[l], insB[l], NX, lng, lnb,
                                          bilin + (size_t)l * D * D,
                                          W_rel + (size_t)l * 3 * D * D,
                                          W_root + (size_t)l * D * D,
                                          bias + (size_t)l * D,
                                          (__half2*)hbhi, (__half2*)hblo,
                                          (__half2*)hhi, HW, outs[l], relu, N);
        zgemm_mma<<<zgrid, 256, SM_TOT>>>((const __half*)hbhi, (const __half*)hblo,
                                          (const __half*)hhi, Zl, N, total_tiles);
        edge_fused<<<edge_blocks, 256>>>(Zl, HW, erow, ecol, etype, eval,
                                         outs[l], Ehalf, N);
    }
}

// round 14
// speedup vs baseline: 1.5951x; 1.0284x over previous
#include <cuda_runtime.h>
#include <cuda_fp16.h>
#include <cstdint>

// ---------------------------------------------------------------------------
// CTDExplainer: 3-layer relational GCN explainer. N=8192, D=64, R=3, E=262144.
// Round 14: ngemm_mma staging de-serialized — ALL global loads (input rows +
// W matrix) are batch-issued into registers via fully unrolled constant-trip
// loops (MLP~40, one latency exposure), then processed. MMA loop and all
// arithmetic bit-identical to round 13. zgemm / edge_fused at measured floors.
// Output layout: [ H (N*64) | z0 (N*N) | z1 | z2 ]  fp32.
// ---------------------------------------------------------------------------

#define MAXN 8192
#define MAXE 262144
#define D 64

__device__ float g_HW  [3 * MAXN * D];
__device__ float g_aggA[MAXN * D];
__device__ float g_aggB[MAXN * D];
__device__ uint2 g_hbhi[MAXN * D / 4];
__device__ uint2 g_hblo[MAXN * D / 4];
__device__ uint2 g_hhi [MAXN * D / 4];

__device__ __forceinline__ uint32_t smem_u32(const void* p) {
    uint32_t a;
    asm("{ .reg .u64 t; cvta.to.shared.u64 t, %1; cvt.u32.u64 %0, t; }" : "=r"(a) : "l"(p));
    return a;
}
__device__ __forceinline__ void ldm_x4(uint32_t& r0, uint32_t& r1, uint32_t& r2,
                                       uint32_t& r3, uint32_t addr) {
    asm volatile("ldmatrix.sync.aligned.m8n8.x4.shared.b16 {%0,%1,%2,%3}, [%4];"
                 : "=r"(r0), "=r"(r1), "=r"(r2), "=r"(r3) : "r"(addr));
}
__device__ __forceinline__ void mma16816(float* c, const uint32_t* a,
                                         uint32_t b0, uint32_t b1) {
    asm volatile(
        "mma.sync.aligned.m16n8k16.row.col.f32.f16.f16.f32 "
        "{%0,%1,%2,%3}, {%4,%5,%6,%7}, {%8,%9}, {%0,%1,%2,%3};"
        : "+f"(c[0]), "+f"(c[1]), "+f"(c[2]), "+f"(c[3])
        : "r"(a[0]), "r"(a[1]), "r"(a[2]), "r"(a[3]), "r"(b0), "r"(b1));
}
__device__ __forceinline__ void cpa16(uint32_t saddr, const void* gaddr) {
    asm volatile("cp.async.cg.shared.global [%0], [%1], 16;"
                 :: "r"(saddr), "l"(gaddr));
}

// ---------------- HMMA per-layer small GEMMs (LN/relu/concat fused) ---------
// grid = (N/64, 5), 128 threads. blockIdx.y selects:
//   0: Hb = base(In) @ bilin -> hbhi/hblo; also exports hhi = fp16(base(In))
//   1..3: HW[y-1] = act(In) @ W_rel[y-1]
//   4: agg = act(In) @ W_root + bias
// 3 fp16 terms: Ihi*Whi + Ilo*Whi + Ihi*Wlo  (error ~2^-22).
#define NG_IHI 0
#define NG_ILO 8192
#define NG_WHI 16384
#define NG_WLO 24576
#define NG_TOT 32768

__global__ void __launch_bounds__(128, 4) ngemm_mma(
    const float* __restrict__ inA, const float* __restrict__ inB, int nxrows,
    const float* __restrict__ lng, const float* __restrict__ lnb,
    const float* __restrict__ bilin, const float* __restrict__ Wrel,
    const float* __restrict__ Wroot, const float* __restrict__ bias,
    __half2* __restrict__ hbhi, __half2* __restrict__ hblo,
    __half2* __restrict__ hhi, float* __restrict__ HW,
    float* __restrict__ agg, int relu, int N) {
    extern __shared__ __align__(16) char smem[];
    const int tid  = threadIdx.x;
    const int row0 = blockIdx.x * 64;
    const int o    = blockIdx.y;
    const uint32_t sb = smem_u32(smem);

    const float* W = (o == 0) ? bilin : (o < 4) ? Wrel + (size_t)(o - 1) * 4096 : Wroot;
    const int act = (o > 0) ? relu : 0;

    // ---- batch-issue ALL global loads first (input rows + W) ----
    const int r    = tid >> 1;
    const int hlf  = tid & 1;
    const int gr   = row0 + r;
    const float* src = (inB && gr >= nxrows)
                     ? (inB + (size_t)(gr - nxrows) * 64 + hlf * 32)
                     : (inA + (size_t)gr * 64 + hlf * 32);
    float v[32];
#pragma unroll
    for (int i = 0; i < 8; i++) {
        float4 t = *(const float4*)(src + i * 4);
        v[i*4+0] = t.x; v[i*4+1] = t.y; v[i*4+2] = t.z; v[i*4+3] = t.w;
    }
    float wv[32];
#pragma unroll
    for (int it = 0; it < 8; it++) {
        const int q  = tid + it * 128;
        const int k0 = (q >> 6) << 2;
        const int n  = q & 63;
#pragma unroll
        for (int j = 0; j < 4; j++)
            wv[it * 4 + j] = __ldg(W + (k0 + j) * 64 + n);
    }

    // ---- process input rows: LN / act / exports, fp16 hi/lo swizzled ----
    {
        if (lng) {
            float s = 0.f, q = 0.f;
#pragma unroll
            for (int i = 0; i < 32; i++) { s += v[i]; q += v[i] * v[i]; }
            s += __shfl_xor_sync(0xffffffffu, s, 1);
            q += __shfl_xor_sync(0xffffffffu, q, 1);
            float mu  = s * (1.f / 64.f);
            float inv = rsqrtf(q * (1.f / 64.f) - mu * mu + 1e-5f);
#pragma unroll
            for (int i = 0; i < 32; i++) {
                int c = hlf * 32 + i;
                v[i] = (v[i] - mu) * inv * lng[c] + lnb[c];
            }
        }
        if (o == 0) {
            if (lng) {
                __half2* dst = hhi + ((size_t)gr * 64 + hlf * 32) / 2;
#pragma unroll
                for (int i = 0; i < 16; i++)
                    dst[i] = __halves2half2(__float2half_rn(v[2*i]),
                                            __float2half_rn(v[2*i+1]));
            } else {
                __half2* dst = hhi + ((size_t)gr * 64 + hlf * 32) / 2;
#pragma unroll
                for (int i = 0; i < 16; i++)
                    dst[i] = __halves2half2(__float2half_rn(v[2*i]),
                                            __float2half_rn(v[2*i+1]));
            }
        } else if (act) {
#pragma unroll
            for (int i = 0; i < 32; i++) v[i] = fmaxf(v[i], 0.f);
        }
        const int r7 = r & 7;
#pragma unroll
        for (int u = 0; u < 4; u++) {
            __half hs[8], ls[8];
#pragma unroll
            for (int j = 0; j < 8; j++) {
                float x = v[u * 8 + j];
                __half h = __float2half_rn(x);
                hs[j] = h;
                ls[j] = __float2half_rn(x - __half2float(h));
            }
            uint32_t unit = (uint32_t)(hlf * 4 + u) ^ (uint32_t)r7;
            uint32_t byte = r * 128 + unit * 16;
            *(uint4*)(smem + NG_IHI + byte) = *(uint4*)hs;
            *(uint4*)(smem + NG_ILO + byte) = *(uint4*)ls;
        }
    }

    // ---- process W: convert + swizzled STS (from registers) ----
#pragma unroll
    for (int it = 0; it < 8; it++) {
        const int q  = tid + it * 128;
        const int k0 = (q >> 6) << 2;
        const int n  = q & 63;
        __half hs[4], ls[4];
#pragma unroll
        for (int j = 0; j < 4; j++) {
            float w = wv[it * 4 + j];
            __half h = __float2half_rn(w);
            hs[j] = h;
            ls[j] = __float2half_rn(w - __half2float(h));
        }
        uint32_t unit = (uint32_t)(k0 >> 3) ^ (uint32_t)(n & 7);
        uint32_t byte = n * 128 + unit * 16 + (k0 & 7) * 2;
        *(uint2*)(smem + NG_WHI + byte) = *(uint2*)hs;
        *(uint2*)(smem + NG_WLO + byte) = *(uint2*)ls;
    }
    __syncthreads();

    // MMA: warp w handles rows wm..wm+15, full n=64
    const int lane = tid & 31;
    const int wid  = tid >> 5;
    const int wm   = wid * 16;
    const int a_row = wm + (lane & 15);
    const int a_r7  = a_row & 7;
    const int au    = lane >> 4;
    const int b_row = (lane & 7) + (((lane >> 4) & 1) << 3);
    const int b_r7  = b_row & 7;
    const int bu    = (lane >> 3) & 1;

    const uint32_t ahib = sb + NG_IHI + a_row * 128;
    const uint32_t alob = sb + NG_ILO + a_row * 128;
    const uint32_t whib = sb + NG_WHI + b_row * 128;
    const uint32_t wlob = sb + NG_WLO + b_row * 128;

    float acc[8][4];
#pragma unroll
    for (int i = 0; i < 8; i++)
#pragma unroll
        for (int j = 0; j < 4; j++) acc[i][j] = 0.f;

#pragma unroll
    for (int kc = 0; kc < 4; kc++) {
        const uint32_t aoff = ((((kc << 1) + au) ^ a_r7) << 4);
        const uint32_t boff = ((((kc << 1) + bu) ^ b_r7) << 4);
        uint32_t Ah[4], Al[4];
        ldm_x4(Ah[0], Ah[1], Ah[2], Ah[3], ahib + aoff);
        ldm_x4(Al[0], Al[1], Al[2], Al[3], alob + aoff);
#pragma unroll
        for (int nt = 0; nt < 4; nt++) {
            uint32_t bh[4], bl[4];
            ldm_x4(bh[0], bh[1], bh[2], bh[3], whib + boff + nt * 16 * 128);
            ldm_x4(bl[0], bl[1], bl[2], bl[3], wlob + boff + nt * 16 * 128);
            float* a0 = acc[2 * nt];
            float* a1 = acc[2 * nt + 1];
            mma16816(a0, Ah, bh[0], bh[1]);
            mma16816(a1, Ah, bh[2], bh[3]);
            mma16816(a0, Al, bh[0], bh[1]);
            mma16816(a1, Al, bh[2], bh[3]);
            mma16816(a0, Ah, bl[0], bl[1]);
            mma16816(a1, Ah, bl[2], bl[3]);
        }
    }

    // epilogue
    const int er = lane >> 2;
    const int ec = (lane & 3) * 2;
    const int gro = row0 + wm + er;
    if (o == 0) {
#pragma unroll
        for (int ni = 0; ni < 8; ni++) {
            float* f = acc[ni];
            int col = ni * 8 + ec;
            size_t i0 = ((size_t)gro * 64 + col) / 2;
            size_t i1 = ((size_t)(gro + 8) * 64 + col) / 2;
            __half h0 = __float2half_rn(f[0]), h1 = __float2half_rn(f[1]);
            __half h2 = __float2half_rn(f[2]), h3 = __float2half_rn(f[3]);
            hbhi[i0] = __halves2half2(h0, h1);
            hbhi[i1] = __halves2half2(h2, h3);
            hblo[i0] = __halves2half2(__float2half_rn(f[0] - __half2float(h0)),
                                      __float2half_rn(f[1] - __half2float(h1)));
            hblo[i1] = __halves2half2(__float2half_rn(f[2] - __half2float(h2)),
                                      __float2half_rn(f[3] - __half2float(h3)));
        }
    } else if (o < 4) {
        float* Out = HW + (size_t)(o - 1) * N * 64;
#pragma unroll
        for (int ni = 0; ni < 8; ni++) {
            float* f = acc[ni];
            int col = ni * 8 + ec;
            *(float2*)(Out + (size_t)gro * 64 + col)       = make_float2(f[0], f[1]);
            *(float2*)(Out + (size_t)(gro + 8) * 64 + col) = make_float2(f[2], f[3]);
        }
    } else {
#pragma unroll
        for (int ni = 0; ni < 8; ni++) {
            float* f = acc[ni];
            int col = ni * 8 + ec;
            float b0 = bias[col], b1 = bias[col + 1];
            *(float2*)(agg + (size_t)gro * 64 + col)       = make_float2(f[0] + b0, f[1] + b1);
            *(float2*)(agg + (size_t)(gro + 8) * 64 + col) = make_float2(f[2] + b0, f[3] + b1);
        }
    }
}

// ---------------- persistent HMMA GEMM: C = (Ahi + Alo) @ Bhi^T -------------
// Band-major tile order; A loaded once per band, B double-buffered cp.async.
#define TILEB 16384
#define SM_TOT (4 * TILEB)

__global__ void __launch_bounds__(256, 2) zgemm_mma(
    const __half* __restrict__ Ahi, const __half* __restrict__ Alo,
    const __half* __restrict__ Bhi, float* __restrict__ C, int N,
    int total_tiles) {
    extern __shared__ __align__(16) char smem[];
    const int tid = threadIdx.x;
    const uint32_t sb = smem_u32(smem);

    const int lrow = tid >> 1;
    const int lcu  = (tid & 1) * 4;
    const int lr7  = lrow & 7;
    const int lcol = (tid & 1) * 32;
    uint32_t soff[4];
#pragma unroll
    for (int i = 0; i < 4; i++)
        soff[i] = lrow * 128 + (((lcu + i) ^ lr7) << 4);

    auto loadA = [&](int band) {
        const __half* gA0 = Ahi + (size_t)(band * 128 + lrow) * 64 + lcol;
        const __half* gA1 = Alo + (size_t)(band * 128 + lrow) * 64 + lcol;
#pragma unroll
        for (int i = 0; i < 4; i++) {
            cpa16(sb + 0 * TILEB + soff[i], gA0 + i * 8);
            cpa16(sb + 1 * TILEB + soff[i], gA1 + i * 8);
        }
    };
    auto issueB = [&](int buf, int n0) {
        const __half* gB = Bhi + (size_t)(n0 * 128 + lrow) * 64 + lcol;
        const uint32_t s0 = sb + 2 * TILEB + buf * TILEB;
#pragma unroll
        for (int i = 0; i < 4; i++)
            cpa16(s0 + soff[i], gB + i * 8);
    };

    const int lane = tid & 31;
    const int wid  = tid >> 5;
    const int wm   = (wid & 3) * 32;
    const int wn   = (wid >> 2) * 64;

    const int a_row = wm + (lane & 15);
    const int a_r7  = a_row & 7;
    const int au    = lane >> 4;
    const int b_row = wn + (lane & 7) + (((lane >> 4) & 1) << 3);
    const int b_r7  = b_row & 7;
    const int bu    = (lane >> 3) & 1;
    const int er = lane >> 2;
    const int ec = (lane & 3) * 2;

    uint32_t aoffk[4], boffk[4];
#pragma unroll
    for (int kc = 0; kc < 4; kc++) {
        aoffk[kc] = ((((kc << 1) + au) ^ a_r7) << 4);
        boffk[kc] = ((((kc << 1) + bu) ^ b_r7) << 4);
    }
    const uint32_t abase_row = sb + a_row * 128;
    const uint32_t bbase0    = sb + 2 * TILEB + b_row * 128;

    const int G = gridDim.x;
    const int p = blockIdx.x;
    const int start = (int)(((long long)p * total_tiles) / G);
    const int end   = (int)(((long long)(p + 1) * total_tiles) / G);
    if (start >= end) return;

    int curBand = start >> 6;
    loadA(curBand);
    issueB(0, start & 63);
    asm volatile("cp.async.commit_group;");

    int idx = 0;
    for (int t = start; t < end; t++, idx++) {
        const int band = t >> 6;
        if (band != curBand) {
            loadA(band);
            asm volatile("cp.async.commit_group;");
            curBand = band;
        }
        const int buf = idx & 1;
        if (t + 1 < end) issueB(1 - buf, (t + 1) & 63);
        asm volatile("cp.async.commit_group;");
        asm volatile("cp.async.wait_group 1;");
        __syncthreads();

        const uint32_t bbase_row = bbase0 + (buf ? (uint32_t)TILEB : 0u);

        float acc[16][4];
#pragma unroll
        for (int i = 0; i < 16; i++)
#pragma unroll
            for (int j = 0; j < 4; j++) acc[i][j] = 0.f;

#pragma unroll
        for (int kc = 0; kc < 4; kc++) {
            uint32_t Ah[8], Al[8], bh[16];
            ldm_x4(Ah[0], Ah[1], Ah[2], Ah[3], abase_row + aoffk[kc]);
            ldm_x4(Ah[4], Ah[5], Ah[6], Ah[7], abase_row + aoffk[kc] + 16 * 128);
            ldm_x4(Al[0], Al[1], Al[2], Al[3], abase_row + TILEB + aoffk[kc]);
            ldm_x4(Al[4], Al[5], Al[6], Al[7], abase_row + TILEB + aoffk[kc] + 16 * 128);
#pragma unroll
            for (int nt2 = 0; nt2 < 4; nt2++)
                ldm_x4(bh[4 * nt2], bh[4 * nt2 + 1], bh[4 * nt2 + 2], bh[4 * nt2 + 3],
                       bbase_row + boffk[kc] + nt2 * 16 * 128);
#pragma unroll
            for (int nt2 = 0; nt2 < 4; nt2++) {
                mma16816(acc[2 * nt2],         Ah,     bh[4 * nt2],     bh[4 * nt2 + 1]);
                mma16816(acc[2 * nt2 + 1],     Ah,     bh[4 * nt2 + 2], bh[4 * nt2 + 3]);
                mma16816(acc[8 + 2 * nt2],     Ah + 4, bh[4 * nt2],     bh[4 * nt2 + 1]);
                mma16816(acc[8 + 2 * nt2 + 1], Ah + 4, bh[4 * nt2 + 2], bh[4 * nt2 + 3]);
            }
#pragma unroll
            for (int nt2 = 0; nt2 < 4; nt2++) {
                mma16816(acc[2 * nt2],         Al,     bh[4 * nt2],     bh[4 * nt2 + 1]);
                mma16816(acc[2 * nt2 + 1],     Al,     bh[4 * nt2 + 2], bh[4 * nt2 + 3]);
                mma16816(acc[8 + 2 * nt2],     Al + 4, bh[4 * nt2],     bh[4 * nt2 + 1]);
                mma16816(acc[8 + 2 * nt2 + 1], Al + 4, bh[4 * nt2 + 2], bh[4 * nt2 + 3]);
            }
        }

        const int m0 = band * 128;
        const int n0 = (t & 63) * 128;
#pragma unroll
        for (int mi = 0; mi < 2; mi++)
#pragma unroll
            for (int ni = 0; ni < 8; ni++) {
                float* f = acc[mi * 8 + ni];
                size_t r = (size_t)(m0 + wm + mi * 16 + er);
                int col = n0 + wn + ni * 8 + ec;
                *(float2*)(C + r * N + col)       = make_float2(f[0], f[1]);
                *(float2*)(C + (r + 8) * N + col) = make_float2(f[2], f[3]);
            }
        __syncthreads();
    }
}

// ---------------- fused edge gather + scatter: 2 edges / 16-lane group ------
__global__ void edge_fused(const float* __restrict__ Z, const float* __restrict__ HW,
                           const int* __restrict__ row, const int* __restrict__ col,
                           const int* __restrict__ et, const float* __restrict__ ev,
                           float* __restrict__ agg, int Ehalf, int N) {
    int gi  = blockIdx.x * blockDim.x + threadIdx.x;
    int e0  = gi >> 4;
    int sub = threadIdx.x & 15;
    if (e0 >= Ehalf) return;
    int e1 = e0 + Ehalf;

    int r0 = row[e0], c0 = col[e0], t0 = et[e0];
    int r1 = row[e1], c1 = col[e1], t1 = et[e1];
    float z0 = Z[(size_t)r0 * N + c0];
    float z1 = Z[(size_t)r1 * N + c1];
    float av0 = z0 * ev[e0];
    float av1 = z1 * ev[e1];
    float4 m0 = ((const float4*)(HW + ((size_t)t0 * N + c0) * 64))[sub];
    float4 m1 = ((const float4*)(HW + ((size_t)t1 * N + c1) * 64))[sub];

    float* d0 = agg + (size_t)r0 * 64 + sub * 4;
    float* d1 = agg + (size_t)r1 * 64 + sub * 4;
    asm volatile("red.global.add.v4.f32 [%0], {%1, %2, %3, %4};"
                 :: "l"(d0), "f"(m0.x * av0), "f"(m0.y * av0),
                    "f"(m0.z * av0), "f"(m0.w * av0) : "memory");
    asm volatile("red.global.add.v4.f32 [%0], {%1, %2, %3, %4};"
                 :: "l"(d1), "f"(m1.x * av1), "f"(m1.y * av1),
                    "f"(m1.z * av1), "f"(m1.w * av1) : "memory");
}

// ---------------------------------------------------------------------------
extern "C" void kernel_launch(void* const* d_in, const int* in_sizes, int n_in,
                              void* d_out, int out_size) {
    const float* x       = (const float*)d_in[0];
    const float* emb     = (const float*)d_in[1];
    const float* bilin   = (const float*)d_in[2];
    const float* eval    = (const float*)d_in[3];
    const float* W_root  = (const float*)d_in[4];
    const float* W_rel   = (const float*)d_in[5];
    const float* bias    = (const float*)d_in[6];
    const float* ln_g    = (const float*)d_in[7];
    const float* ln_b    = (const float*)d_in[8];
    const int*   erow    = (const int*)d_in[9];
    const int*   ecol    = (const int*)d_in[10];
    const int*   etype   = (const int*)d_in[11];

    const int NX = in_sizes[0] / D;
    const int NE = in_sizes[1] / D;
    const int N  = NX + NE;
    const int E  = in_sizes[3];

    float* out   = (float*)d_out;
    float* Hout  = out;
    float* Zbase = out + (size_t)N * D;

    float *HW, *aggA, *aggB;
    uint2 *hbhi, *hblo, *hhi;
    cudaGetSymbolAddress((void**)&HW,   g_HW);
    cudaGetSymbolAddress((void**)&aggA, g_aggA);
    cudaGetSymbolAddress((void**)&aggB, g_aggB);
    cudaGetSymbolAddress((void**)&hbhi, g_hbhi);
    cudaGetSymbolAddress((void**)&hblo, g_hblo);
    cudaGetSymbolAddress((void**)&hhi,  g_hhi);

    cudaFuncSetAttribute(zgemm_mma, cudaFuncAttributeMaxDynamicSharedMemorySize, SM_TOT);
    cudaFuncSetAttribute(ngemm_mma, cudaFuncAttributeMaxDynamicSharedMemorySize, NG_TOT);

    int nsm = 148;
    cudaDeviceGetAttribute(&nsm, cudaDevAttrMultiProcessorCount, 0);

    const int tiles_n = N / 128;
    const int total_tiles = tiles_n * tiles_n;
    const int zgrid = 2 * nsm;
    dim3 ngrid(N / 64, 5);
    const int Ehalf = E / 2;
    const int edge_blocks = (Ehalf * 16 + 255) / 256;

    const float* insA[3] = { x, aggA, aggB };
    const float* insB[3] = { emb, nullptr, nullptr };
    float*       outs[3] = { aggA, aggB, Hout };

    for (int l = 0; l < 3; l++) {
        float* Zl   = Zbase + (size_t)l * N * N;
        const float* lng = (l == 0) ? nullptr : ln_g + (size_t)(l - 1) * D;
        const float* lnb = (l == 0) ? nullptr : ln_b + (size_t)(l - 1) * D;
        int relu = (l > 0) ? 1 : 0;

        ngemm_mma<<<ngrid, 128, NG_TOT>>>(insA[l], insB[l], NX, lng, lnb,
                                          bilin + (size_t)l * D * D,
                                          W_rel + (size_t)l * 3 * D * D,
                                          W_root + (size_t)l * D * D,
                                          bias + (size_t)l * D,
                                          (__half2*)hbhi, (__half2*)hblo,
                                          (__half2*)hhi, HW, outs[l], relu, N);
        zgemm_mma<<<zgrid, 256, SM_TOT>>>((const __half*)hbhi, (const __half*)hblo,
                                          (const __half*)hhi, Zl, N, total_tiles);
        edge_fused<<<edge_blocks, 256>>>(Zl, HW, erow, ecol, etype, eval,
                                         outs[l], Ehalf, N);
    }
}

// round 15
// speedup vs baseline: 1.6075x; 1.0078x over previous
#include <cuda_runtime.h>
#include <cuda_fp16.h>
#include <cstdint>

// ---------------------------------------------------------------------------
// CTDExplainer: 3-layer relational GCN explainer. N=8192, D=64, R=3, E=262144.
// Round 15: graph fork — per layer, ngemm outputs o=1..4 (HW, agg) run on a
// second captured stream overlapping ngemm_o0 + zgemm on the main stream;
// main stream joins before edge_fused. Kernel arithmetic identical to r14.
// Output layout: [ H (N*64) | z0 (N*N) | z1 | z2 ]  fp32.
// ---------------------------------------------------------------------------

#define MAXN 8192
#define MAXE 262144
#define D 64

__device__ float g_HW  [3 * MAXN * D];
__device__ float g_aggA[MAXN * D];
__device__ float g_aggB[MAXN * D];
__device__ uint2 g_hbhi[MAXN * D / 4];
__device__ uint2 g_hblo[MAXN * D / 4];
__device__ uint2 g_hhi [MAXN * D / 4];

__device__ __forceinline__ uint32_t smem_u32(const void* p) {
    uint32_t a;
    asm("{ .reg .u64 t; cvta.to.shared.u64 t, %1; cvt.u32.u64 %0, t; }" : "=r"(a) : "l"(p));
    return a;
}
__device__ __forceinline__ void ldm_x4(uint32_t& r0, uint32_t& r1, uint32_t& r2,
                                       uint32_t& r3, uint32_t addr) {
    asm volatile("ldmatrix.sync.aligned.m8n8.x4.shared.b16 {%0,%1,%2,%3}, [%4];"
                 : "=r"(r0), "=r"(r1), "=r"(r2), "=r"(r3) : "r"(addr));
}
__device__ __forceinline__ void mma16816(float* c, const uint32_t* a,
                                         uint32_t b0, uint32_t b1) {
    asm volatile(
        "mma.sync.aligned.m16n8k16.row.col.f32.f16.f16.f32 "
        "{%0,%1,%2,%3}, {%4,%5,%6,%7}, {%8,%9}, {%0,%1,%2,%3};"
        : "+f"(c[0]), "+f"(c[1]), "+f"(c[2]), "+f"(c[3])
        : "r"(a[0]), "r"(a[1]), "r"(a[2]), "r"(a[3]), "r"(b0), "r"(b1));
}
__device__ __forceinline__ void cpa16(uint32_t saddr, const void* gaddr) {
    asm volatile("cp.async.cg.shared.global [%0], [%1], 16;"
                 :: "r"(saddr), "l"(gaddr));
}

// ---------------- HMMA per-layer small GEMMs (LN/relu/concat fused) ---------
// grid = (N/64, ny), o = blockIdx.y + obase:
//   0: Hb = base(In) @ bilin -> hbhi/hblo; also exports hhi = fp16(base(In))
//   1..3: HW[o-1] = act(In) @ W_rel[o-1]
//   4: agg = act(In) @ W_root + bias
#define NG_IHI 0
#define NG_ILO 8192
#define NG_WHI 16384
#define NG_WLO 24576
#define NG_TOT 32768

__global__ void __launch_bounds__(128, 4) ngemm_mma(
    const float* __restrict__ inA, const float* __restrict__ inB, int nxrows,
    const float* __restrict__ lng, const float* __restrict__ lnb,
    const float* __restrict__ bilin, const float* __restrict__ Wrel,
    const float* __restrict__ Wroot, const float* __restrict__ bias,
    __half2* __restrict__ hbhi, __half2* __restrict__ hblo,
    __half2* __restrict__ hhi, float* __restrict__ HW,
    float* __restrict__ agg, int relu, int N, int obase) {
    extern __shared__ __align__(16) char smem[];
    const int tid  = threadIdx.x;
    const int row0 = blockIdx.x * 64;
    const int o    = blockIdx.y + obase;
    const uint32_t sb = smem_u32(smem);

    const float* W = (o == 0) ? bilin : (o < 4) ? Wrel + (size_t)(o - 1) * 4096 : Wroot;
    const int act = (o > 0) ? relu : 0;

    // ---- batch-issue ALL global loads first (input rows + W) ----
    const int r    = tid >> 1;
    const int hlf  = tid & 1;
    const int gr   = row0 + r;
    const float* src = (inB && gr >= nxrows)
                     ? (inB + (size_t)(gr - nxrows) * 64 + hlf * 32)
                     : (inA + (size_t)gr * 64 + hlf * 32);
    float v[32];
#pragma unroll
    for (int i = 0; i < 8; i++) {
        float4 t = *(const float4*)(src + i * 4);
        v[i*4+0] = t.x; v[i*4+1] = t.y; v[i*4+2] = t.z; v[i*4+3] = t.w;
    }
    float wv[32];
#pragma unroll
    for (int it = 0; it < 8; it++) {
        const int q  = tid + it * 128;
        const int k0 = (q >> 6) << 2;
        const int n  = q & 63;
#pragma unroll
        for (int j = 0; j < 4; j++)
            wv[it * 4 + j] = __ldg(W + (k0 + j) * 64 + n);
    }

    // ---- process input rows: LN / act / exports, fp16 hi/lo swizzled ----
    {
        if (lng) {
            float s = 0.f, q = 0.f;
#pragma unroll
            for (int i = 0; i < 32; i++) { s += v[i]; q += v[i] * v[i]; }
            s += __shfl_xor_sync(0xffffffffu, s, 1);
            q += __shfl_xor_sync(0xffffffffu, q, 1);
            float mu  = s * (1.f / 64.f);
            float inv = rsqrtf(q * (1.f / 64.f) - mu * mu + 1e-5f);
#pragma unroll
            for (int i = 0; i < 32; i++) {
                int c = hlf * 32 + i;
                v[i] = (v[i] - mu) * inv * lng[c] + lnb[c];
            }
        }
        if (o == 0) {
            __half2* dst = hhi + ((size_t)gr * 64 + hlf * 32) / 2;
#pragma unroll
            for (int i = 0; i < 16; i++)
                dst[i] = __halves2half2(__float2half_rn(v[2*i]),
                                        __float2half_rn(v[2*i+1]));
        } else if (act) {
#pragma unroll
            for (int i = 0; i < 32; i++) v[i] = fmaxf(v[i], 0.f);
        }
        const int r7 = r & 7;
#pragma unroll
        for (int u = 0; u < 4; u++) {
            __half hs[8], ls[8];
#pragma unroll
            for (int j = 0; j < 8; j++) {
                float x = v[u * 8 + j];
                __half h = __float2half_rn(x);
                hs[j] = h;
                ls[j] = __float2half_rn(x - __half2float(h));
            }
            uint32_t unit = (uint32_t)(hlf * 4 + u) ^ (uint32_t)r7;
            uint32_t byte = r * 128 + unit * 16;
            *(uint4*)(smem + NG_IHI + byte) = *(uint4*)hs;
            *(uint4*)(smem + NG_ILO + byte) = *(uint4*)ls;
        }
    }

    // ---- process W: convert + swizzled STS (from registers) ----
#pragma unroll
    for (int it = 0; it < 8; it++) {
        const int q  = tid + it * 128;
        const int k0 = (q >> 6) << 2;
        const int n  = q & 63;
        __half hs[4], ls[4];
#pragma unroll
        for (int j = 0; j < 4; j++) {
            float w = wv[it * 4 + j];
            __half h = __float2half_rn(w);
            hs[j] = h;
            ls[j] = __float2half_rn(w - __half2float(h));
        }
        uint32_t unit = (uint32_t)(k0 >> 3) ^ (uint32_t)(n & 7);
        uint32_t byte = n * 128 + unit * 16 + (k0 & 7) * 2;
        *(uint2*)(smem + NG_WHI + byte) = *(uint2*)hs;
        *(uint2*)(smem + NG_WLO + byte) = *(uint2*)ls;
    }
    __syncthreads();

    // MMA: warp w handles rows wm..wm+15, full n=64
    const int lane = tid & 31;
    const int wid  = tid >> 5;
    const int wm   = wid * 16;
    const int a_row = wm + (lane & 15);
    const int a_r7  = a_row & 7;
    const int au    = lane >> 4;
    const int b_row = (lane & 7) + (((lane >> 4) & 1) << 3);
    const int b_r7  = b_row & 7;
    const int bu    = (lane >> 3) & 1;

    const uint32_t ahib = sb + NG_IHI + a_row * 128;
    const uint32_t alob = sb + NG_ILO + a_row * 128;
    const uint32_t whib = sb + NG_WHI + b_row * 128;
    const uint32_t wlob = sb + NG_WLO + b_row * 128;

    float acc[8][4];
#pragma unroll
    for (int i = 0; i < 8; i++)
#pragma unroll
        for (int j = 0; j < 4; j++) acc[i][j] = 0.f;

#pragma unroll
    for (int kc = 0; kc < 4; kc++) {
        const uint32_t aoff = ((((kc << 1) + au) ^ a_r7) << 4);
        const uint32_t boff = ((((kc << 1) + bu) ^ b_r7) << 4);
        uint32_t Ah[4], Al[4];
        ldm_x4(Ah[0], Ah[1], Ah[2], Ah[3], ahib + aoff);
        ldm_x4(Al[0], Al[1], Al[2], Al[3], alob + aoff);
#pragma unroll
        for (int nt = 0; nt < 4; nt++) {
            uint32_t bh[4], bl[4];
            ldm_x4(bh[0], bh[1], bh[2], bh[3], whib + boff + nt * 16 * 128);
            ldm_x4(bl[0], bl[1], bl[2], bl[3], wlob + boff + nt * 16 * 128);
            float* a0 = acc[2 * nt];
            float* a1 = acc[2 * nt + 1];
            mma16816(a0, Ah, bh[0], bh[1]);
            mma16816(a1, Ah, bh[2], bh[3]);
            mma16816(a0, Al, bh[0], bh[1]);
            mma16816(a1, Al, bh[2], bh[3]);
            mma16816(a0, Ah, bl[0], bl[1]);
            mma16816(a1, Ah, bl[2], bl[3]);
        }
    }

    // epilogue
    const int er = lane >> 2;
    const int ec = (lane & 3) * 2;
    const int gro = row0 + wm + er;
    if (o == 0) {
#pragma unroll
        for (int ni = 0; ni < 8; ni++) {
            float* f = acc[ni];
            int col = ni * 8 + ec;
            size_t i0 = ((size_t)gro * 64 + col) / 2;
            size_t i1 = ((size_t)(gro + 8) * 64 + col) / 2;
            __half h0 = __float2half_rn(f[0]), h1 = __float2half_rn(f[1]);
            __half h2 = __float2half_rn(f[2]), h3 = __float2half_rn(f[3]);
            hbhi[i0] = __halves2half2(h0, h1);
            hbhi[i1] = __halves2half2(h2, h3);
            hblo[i0] = __halves2half2(__float2half_rn(f[0] - __half2float(h0)),
                                      __float2half_rn(f[1] - __half2float(h1)));
            hblo[i1] = __halves2half2(__float2half_rn(f[2] - __half2float(h2)),
                                      __float2half_rn(f[3] - __half2float(h3)));
        }
    } else if (o < 4) {
        float* Out = HW + (size_t)(o - 1) * N * 64;
#pragma unroll
        for (int ni = 0; ni < 8; ni++) {
            float* f = acc[ni];
            int col = ni * 8 + ec;
            *(float2*)(Out + (size_t)gro * 64 + col)       = make_float2(f[0], f[1]);
            *(float2*)(Out + (size_t)(gro + 8) * 64 + col) = make_float2(f[2], f[3]);
        }
    } else {
#pragma unroll
        for (int ni = 0; ni < 8; ni++) {
            float* f = acc[ni];
            int col = ni * 8 + ec;
            float b0 = bias[col], b1 = bias[col + 1];
            *(float2*)(agg + (size_t)gro * 64 + col)       = make_float2(f[0] + b0, f[1] + b1);
            *(float2*)(agg + (size_t)(gro + 8) * 64 + col) = make_float2(f[2] + b0, f[3] + b1);
        }
    }
}

// ---------------- persistent HMMA GEMM: C = (Ahi + Alo) @ Bhi^T -------------
#define TILEB 16384
#define SM_TOT (4 * TILEB)

__global__ void __launch_bounds__(256, 2) zgemm_mma(
    const __half* __restrict__ Ahi, const __half* __restrict__ Alo,
    const __half* __restrict__ Bhi, float* __restrict__ C, int N,
    int total_tiles) {
    extern __shared__ __align__(16) char smem[];
    const int tid = threadIdx.x;
    const uint32_t sb = smem_u32(smem);

    const int lrow = tid >> 1;
    const int lcu  = (tid & 1) * 4;
    const int lr7  = lrow & 7;
    const int lcol = (tid & 1) * 32;
    uint32_t soff[4];
#pragma unroll
    for (int i = 0; i < 4; i++)
        soff[i] = lrow * 128 + (((lcu + i) ^ lr7) << 4);

    auto loadA = [&](int band) {
        const __half* gA0 = Ahi + (size_t)(band * 128 + lrow) * 64 + lcol;
        const __half* gA1 = Alo + (size_t)(band * 128 + lrow) * 64 + lcol;
#pragma unroll
        for (int i = 0; i < 4; i++) {
            cpa16(sb + 0 * TILEB + soff[i], gA0 + i * 8);
            cpa16(sb + 1 * TILEB + soff[i], gA1 + i * 8);
        }
    };
    auto issueB = [&](int buf, int n0) {
        const __half* gB = Bhi + (size_t)(n0 * 128 + lrow) * 64 + lcol;
        const uint32_t s0 = sb + 2 * TILEB + buf * TILEB;
#pragma unroll
        for (int i = 0; i < 4; i++)
            cpa16(s0 + soff[i], gB + i * 8);
    };

    const int lane = tid & 31;
    const int wid  = tid >> 5;
    const int wm   = (wid & 3) * 32;
    const int wn   = (wid >> 2) * 64;

    const int a_row = wm + (lane & 15);
    const int a_r7  = a_row & 7;
    const int au    = lane >> 4;
    const int b_row = wn + (lane & 7) + (((lane >> 4) & 1) << 3);
    const int b_r7  = b_row & 7;
    const int bu    = (lane >> 3) & 1;
    const int er = lane >> 2;
    const int ec = (lane & 3) * 2;

    uint32_t aoffk[4], boffk[4];
#pragma unroll
    for (int kc = 0; kc < 4; kc++) {
        aoffk[kc] = ((((kc << 1) + au) ^ a_r7) << 4);
        boffk[kc] = ((((kc << 1) + bu) ^ b_r7) << 4);
    }
    const uint32_t abase_row = sb + a_row * 128;
    const uint32_t bbase0    = sb + 2 * TILEB + b_row * 128;

    const int G = gridDim.x;
    const int p = blockIdx.x;
    const int start = (int)(((long long)p * total_tiles) / G);
    const int end   = (int)(((long long)(p + 1) * total_tiles) / G);
    if (start >= end) return;

    int curBand = start >> 6;
    loadA(curBand);
    issueB(0, start & 63);
    asm volatile("cp.async.commit_group;");

    int idx = 0;
    for (int t = start; t < end; t++, idx++) {
        const int band = t >> 6;
        if (band != curBand) {
            loadA(band);
            asm volatile("cp.async.commit_group;");
            curBand = band;
        }
        const int buf = idx & 1;
        if (t + 1 < end) issueB(1 - buf, (t + 1) & 63);
        asm volatile("cp.async.commit_group;");
        asm volatile("cp.async.wait_group 1;");
        __syncthreads();

        const uint32_t bbase_row = bbase0 + (buf ? (uint32_t)TILEB : 0u);

        float acc[16][4];
#pragma unroll
        for (int i = 0; i < 16; i++)
#pragma unroll
            for (int j = 0; j < 4; j++) acc[i][j] = 0.f;

#pragma unroll
        for (int kc = 0; kc < 4; kc++) {
            uint32_t Ah[8], Al[8], bh[16];
            ldm_x4(Ah[0], Ah[1], Ah[2], Ah[3], abase_row + aoffk[kc]);
            ldm_x4(Ah[4], Ah[5], Ah[6], Ah[7], abase_row + aoffk[kc] + 16 * 128);
            ldm_x4(Al[0], Al[1], Al[2], Al[3], abase_row + TILEB + aoffk[kc]);
            ldm_x4(Al[4], Al[5], Al[6], Al[7], abase_row + TILEB + aoffk[kc] + 16 * 128);
#pragma unroll
            for (int nt2 = 0; nt2 < 4; nt2++)
                ldm_x4(bh[4 * nt2], bh[4 * nt2 + 1], bh[4 * nt2 + 2], bh[4 * nt2 + 3],
                       bbase_row + boffk[kc] + nt2 * 16 * 128);
#pragma unroll
            for (int nt2 = 0; nt2 < 4; nt2++) {
                mma16816(acc[2 * nt2],         Ah,     bh[4 * nt2],     bh[4 * nt2 + 1]);
                mma16816(acc[2 * nt2 + 1],     Ah,     bh[4 * nt2 + 2], bh[4 * nt2 + 3]);
                mma16816(acc[8 + 2 * nt2],     Ah + 4, bh[4 * nt2],     bh[4 * nt2 + 1]);
                mma16816(acc[8 + 2 * nt2 + 1], Ah + 4, bh[4 * nt2 + 2], bh[4 * nt2 + 3]);
            }
#pragma unroll
            for (int nt2 = 0; nt2 < 4; nt2++) {
                mma16816(acc[2 * nt2],         Al,     bh[4 * nt2],     bh[4 * nt2 + 1]);
                mma16816(acc[2 * nt2 + 1],     Al,     bh[4 * nt2 + 2], bh[4 * nt2 + 3]);
                mma16816(acc[8 + 2 * nt2],     Al + 4, bh[4 * nt2],     bh[4 * nt2 + 1]);
                mma16816(acc[8 + 2 * nt2 + 1], Al + 4, bh[4 * nt2 + 2], bh[4 * nt2 + 3]);
            }
        }

        const int m0 = band * 128;
        const int n0 = (t & 63) * 128;
#pragma unroll
        for (int mi = 0; mi < 2; mi++)
#pragma unroll
            for (int ni = 0; ni < 8; ni++) {
                float* f = acc[mi * 8 + ni];
                size_t rr = (size_t)(m0 + wm + mi * 16 + er);
                int col = n0 + wn + ni * 8 + ec;
                *(float2*)(C + rr * N + col)       = make_float2(f[0], f[1]);
                *(float2*)(C + (rr + 8) * N + col) = make_float2(f[2], f[3]);
            }
        __syncthreads();
    }
}

// ---------------- fused edge gather + scatter: 2 edges / 16-lane group ------
__global__ void edge_fused(const float* __restrict__ Z, const float* __restrict__ HW,
                           const int* __restrict__ row, const int* __restrict__ col,
                           const int* __restrict__ et, const float* __restrict__ ev,
                           float* __restrict__ agg, int Ehalf, int N) {
    int gi  = blockIdx.x * blockDim.x + threadIdx.x;
    int e0  = gi >> 4;
    int sub = threadIdx.x & 15;
    if (e0 >= Ehalf) return;
    int e1 = e0 + Ehalf;

    int r0 = row[e0], c0 = col[e0], t0 = et[e0];
    int r1 = row[e1], c1 = col[e1], t1 = et[e1];
    float z0 = Z[(size_t)r0 * N + c0];
    float z1 = Z[(size_t)r1 * N + c1];
    float av0 = z0 * ev[e0];
    float av1 = z1 * ev[e1];
    float4 m0 = ((const float4*)(HW + ((size_t)t0 * N + c0) * 64))[sub];
    float4 m1 = ((const float4*)(HW + ((size_t)t1 * N + c1) * 64))[sub];

    float* d0 = agg + (size_t)r0 * 64 + sub * 4;
    float* d1 = agg + (size_t)r1 * 64 + sub * 4;
    asm volatile("red.global.add.v4.f32 [%0], {%1, %2, %3, %4};"
                 :: "l"(d0), "f"(m0.x * av0), "f"(m0.y * av0),
                    "f"(m0.z * av0), "f"(m0.w * av0) : "memory");
    asm volatile("red.global.add.v4.f32 [%0], {%1, %2, %3, %4};"
                 :: "l"(d1), "f"(m1.x * av1), "f"(m1.y * av1),
                    "f"(m1.z * av1), "f"(m1.w * av1) : "memory");
}

// ---------------------------------------------------------------------------
extern "C" void kernel_launch(void* const* d_in, const int* in_sizes, int n_in,
                              void* d_out, int out_size) {
    const float* x       = (const float*)d_in[0];
    const float* emb     = (const float*)d_in[1];
    const float* bilin   = (const float*)d_in[2];
    const float* eval    = (const float*)d_in[3];
    const float* W_root  = (const float*)d_in[4];
    const float* W_rel   = (const float*)d_in[5];
    const float* bias    = (const float*)d_in[6];
    const float* ln_g    = (const float*)d_in[7];
    const float* ln_b    = (const float*)d_in[8];
    const int*   erow    = (const int*)d_in[9];
    const int*   ecol    = (const int*)d_in[10];
    const int*   etype   = (const int*)d_in[11];

    const int NX = in_sizes[0] / D;
    const int NE = in_sizes[1] / D;
    const int N  = NX + NE;
    const int E  = in_sizes[3];

    float* out   = (float*)d_out;
    float* Hout  = out;
    float* Zbase = out + (size_t)N * D;

    float *HW, *aggA, *aggB;
    uint2 *hbhi, *hblo, *hhi;
    cudaGetSymbolAddress((void**)&HW,   g_HW);
    cudaGetSymbolAddress((void**)&aggA, g_aggA);
    cudaGetSymbolAddress((void**)&aggB, g_aggB);
    cudaGetSymbolAddress((void**)&hbhi, g_hbhi);
    cudaGetSymbolAddress((void**)&hblo, g_hblo);
    cudaGetSymbolAddress((void**)&hhi,  g_hhi);

    cudaFuncSetAttribute(zgemm_mma, cudaFuncAttributeMaxDynamicSharedMemorySize, SM_TOT);
    cudaFuncSetAttribute(ngemm_mma, cudaFuncAttributeMaxDynamicSharedMemorySize, NG_TOT);

    static cudaStream_t s2 = nullptr;
    static cudaEvent_t evFork = nullptr, evRest = nullptr;
    if (!s2) {
        cudaStreamCreateWithFlags(&s2, cudaStreamNonBlocking);
        cudaEventCreateWithFlags(&evFork, cudaEventDisableTiming);
        cudaEventCreateWithFlags(&evRest, cudaEventDisableTiming);
    }

    int nsm = 148;
    cudaDeviceGetAttribute(&nsm, cudaDevAttrMultiProcessorCount, 0);

    const int tiles_n = N / 128;
    const int total_tiles = tiles_n * tiles_n;
    const int zgrid = 2 * nsm;
    const int Ehalf = E / 2;
    const int edge_blocks = (Ehalf * 16 + 255) / 256;

    const float* insA[3] = { x, aggA, aggB };
    const float* insB[3] = { emb, nullptr, nullptr };
    float*       outs[3] = { aggA, aggB, Hout };

    for (int l = 0; l < 3; l++) {
        float* Zl   = Zbase + (size_t)l * N * N;
        const float* lng = (l == 0) ? nullptr : ln_g + (size_t)(l - 1) * D;
        const float* lnb = (l == 0) ? nullptr : ln_b + (size_t)(l - 1) * D;
        int relu = (l > 0) ? 1 : 0;

        // fork: HW + agg (o=1..4) on s2, overlapping o=0 + zgemm on main
        cudaEventRecord(evFork, 0);
        cudaStreamWaitEvent(s2, evFork, 0);
        ngemm_mma<<<dim3(N / 64, 4), 128, NG_TOT, s2>>>(
            insA[l], insB[l], NX, lng, lnb,
            bilin + (size_t)l * D * D, W_rel + (size_t)l * 3 * D * D,
            W_root + (size_t)l * D * D, bias + (size_t)l * D,
            (__half2*)hbhi, (__half2*)hblo, (__half2*)hhi,
            HW, outs[l], relu, N, /*obase=*/1);
        cudaEventRecord(evRest, s2);

        ngemm_mma<<<dim3(N / 64, 1), 128, NG_TOT>>>(
            insA[l], insB[l], NX, lng, lnb,
            bilin + (size_t)l * D * D, W_rel + (size_t)l * 3 * D * D,
            W_root + (size_t)l * D * D, bias + (size_t)l * D,
            (__half2*)hbhi, (__half2*)hblo, (__half2*)hhi,
            HW, outs[l], relu, N, /*obase=*/0);
        zgemm_mma<<<zgrid, 256, SM_TOT>>>((const __half*)hbhi, (const __half*)hblo,
                                          (const __half*)hhi, Zl, N, total_tiles);

        // join: edge needs Z, HW, and agg
        cudaStreamWaitEvent(0, evRest, 0);
        edge_fused<<<edge_blocks, 256>>>(Zl, HW, erow, ecol, etype, eval,
                                         outs[l], Ehalf, N);
    }
}